// round 1
// baseline (speedup 1.0000x reference)
#include <cuda_runtime.h>
#include <math.h>

// Problem constants
#define Bv   2
#define Sv   2048
#define Hv   1024
#define NHv  16
#define HDv  64
#define H3   (3 * Hv)
#define MSEQ (Bv * Sv)          // 4096 rows

// Scratch (device globals: allocation-guard safe)
__device__ float g_qkv[(size_t)MSEQ * H3];   // [B*S, 3H]
__device__ float g_av [(size_t)MSEQ * Hv];   // [B*S, H]

// ============================================================================
// GEMM (NT): C[m,n] = sum_k A[m,k] * W[n,k] + bias[n]
// BM=BN=128, BK=16, 256 threads, 8x8 per-thread microtile.
// ============================================================================
#define BM 128
#define BN 128
#define BK 16
#define LDS_ (BM + 4)           // padded k-major stride

__global__ __launch_bounds__(256)
void gemm_nt_bias(const float* __restrict__ A, const float* __restrict__ W,
                  const float* __restrict__ bias, float* __restrict__ C,
                  int M, int N, int K)
{
    __shared__ float As[BK][LDS_];
    __shared__ float Bs[BK][LDS_];

    const int tid = threadIdx.x;
    const int tx  = tid & 15;       // 0..15 -> n
    const int ty  = tid >> 4;       // 0..15 -> m
    const int m0  = blockIdx.y * BM;
    const int n0  = blockIdx.x * BN;

    float acc[8][8];
#pragma unroll
    for (int i = 0; i < 8; i++)
#pragma unroll
        for (int j = 0; j < 8; j++) acc[i][j] = 0.f;

    for (int k0 = 0; k0 < K; k0 += BK) {
        // Load tiles: 128 rows x 16 cols each = 512 float4; 2 float4 per thread.
#pragma unroll
        for (int l = 0; l < 2; l++) {
            int idx = tid + l * 256;          // 0..511
            int row = idx >> 2;               // 0..127
            int jv  = (idx & 3) << 2;         // 0,4,8,12
            float4 va = *(const float4*)(A + (size_t)(m0 + row) * K + k0 + jv);
            As[jv + 0][row] = va.x; As[jv + 1][row] = va.y;
            As[jv + 2][row] = va.z; As[jv + 3][row] = va.w;
            float4 vb = *(const float4*)(W + (size_t)(n0 + row) * K + k0 + jv);
            Bs[jv + 0][row] = vb.x; Bs[jv + 1][row] = vb.y;
            Bs[jv + 2][row] = vb.z; Bs[jv + 3][row] = vb.w;
        }
        __syncthreads();

#pragma unroll
        for (int kk = 0; kk < BK; kk++) {
            float a[8], b[8];
            *(float4*)&a[0] = *(const float4*)&As[kk][ty * 8];
            *(float4*)&a[4] = *(const float4*)&As[kk][ty * 8 + 4];
            *(float4*)&b[0] = *(const float4*)&Bs[kk][tx * 8];
            *(float4*)&b[4] = *(const float4*)&Bs[kk][tx * 8 + 4];
#pragma unroll
            for (int i = 0; i < 8; i++)
#pragma unroll
                for (int j = 0; j < 8; j++)
                    acc[i][j] += a[i] * b[j];
        }
        __syncthreads();
    }

    // Epilogue: bias + store (float4)
#pragma unroll
    for (int i = 0; i < 8; i++) {
        int m = m0 + ty * 8 + i;
#pragma unroll
        for (int j = 0; j < 8; j += 4) {
            int n = n0 + tx * 8 + j;
            float4 v;
            v.x = acc[i][j + 0] + bias[n + 0];
            v.y = acc[i][j + 1] + bias[n + 1];
            v.z = acc[i][j + 2] + bias[n + 2];
            v.w = acc[i][j + 3] + bias[n + 3];
            *(float4*)(C + (size_t)m * N + n) = v;
        }
    }
}

// ============================================================================
// Flash attention, fp32. One block = (batch b, head h, 64 q-rows).
// Q/K stored d-major ([d][col]) with XOR swizzle on the column-group to cut
// transpose-store conflicts; V stored row-major (conflict-free). P reuses the
// K buffer. m/l tracked redundantly in registers per 16-lane row group.
// Exactly 48KB static shared.
// ============================================================================
__global__ __launch_bounds__(256)
void attn_kernel(const float* __restrict__ qkv, const float* __restrict__ mask,
                 float* __restrict__ av)
{
    __shared__ float Qs[HDv * 64];   // Qs[d*64 + swz(d, r)]
    __shared__ float KP[HDv * 64];   // K: [d*64 + swz(d, c)]  then  P: [r*64 + c]
    __shared__ float Vs[64 * HDv];   // Vs[k*64 + d]

    const int tid = threadIdx.x;
    const int tx  = tid & 15;        // -> k-cols / d-cols
    const int ty  = tid >> 4;        // -> q-rows
    const int q0  = blockIdx.x * 64;
    const int h   = blockIdx.y;
    const int b   = blockIdx.z;
    const int r0  = ty * 4;
    const int c0  = tx * 4;
    const size_t base = (size_t)b * Sv * H3 + (size_t)h * HDv;

    // ---- Load Q tile transposed+swizzled (once per block) ----
#pragma unroll
    for (int l = 0; l < 4; l++) {
        int idx = tid + l * 256;         // 0..1023
        int r   = idx >> 4;              // 0..63 (seq row in tile)
        int dv  = (idx & 15) << 2;       // 0,4,...,60
        float4 v = *(const float4*)(qkv + base + (size_t)(q0 + r) * H3 + dv);
        float vv[4] = {v.x, v.y, v.z, v.w};
#pragma unroll
        for (int e = 0; e < 4; e++) {
            int d = dv + e;
            Qs[d * 64 + ((((r >> 2) ^ (d & 15)) << 2) | (r & 3))] = vv[e];
        }
    }

    float m_i[4], l_i[4], o[4][4];
#pragma unroll
    for (int i = 0; i < 4; i++) {
        m_i[i] = -INFINITY; l_i[i] = 0.f;
#pragma unroll
        for (int j = 0; j < 4; j++) o[i][j] = 0.f;
    }

    for (int kt = 0; kt < Sv / 64; kt++) {
        const int kb = kt * 64;
        __syncthreads();   // previous iteration's P/V reads finished

        // ---- Load K (transposed+swizzled) and V (row-major) ----
#pragma unroll
        for (int l = 0; l < 4; l++) {
            int idx = tid + l * 256;
            int r   = idx >> 4;
            int dv  = (idx & 15) << 2;
            const float* kp = qkv + base + (size_t)(kb + r) * H3 + Hv + dv;
            float4 k4 = *(const float4*)kp;
            float kvv[4] = {k4.x, k4.y, k4.z, k4.w};
#pragma unroll
            for (int e = 0; e < 4; e++) {
                int d = dv + e;
                KP[d * 64 + ((((r >> 2) ^ (d & 15)) << 2) | (r & 3))] = kvv[e];
            }
            float4 v4 = *(const float4*)(kp + Hv);   // V at offset 2H
            *(float4*)&Vs[r * 64 + dv] = v4;
        }
        __syncthreads();

        // ---- S = Q K^T (4x4 per thread) ----
        float s[4][4];
#pragma unroll
        for (int i = 0; i < 4; i++)
#pragma unroll
            for (int j = 0; j < 4; j++) s[i][j] = 0.f;

#pragma unroll 16
        for (int d = 0; d < HDv; d++) {
            float4 qa = *(const float4*)&Qs[d * 64 + ((ty ^ (d & 15)) << 2)];
            float4 ka = *(const float4*)&KP[d * 64 + ((tx ^ (d & 15)) << 2)];
            float qs[4] = {qa.x, qa.y, qa.z, qa.w};
            float ks[4] = {ka.x, ka.y, ka.z, ka.w};
#pragma unroll
            for (int i = 0; i < 4; i++)
#pragma unroll
                for (int j = 0; j < 4; j++)
                    s[i][j] += qs[i] * ks[j];
        }

        // ---- mask + scale + online softmax ----
        float mk[4];
#pragma unroll
        for (int j = 0; j < 4; j++) mk[j] = mask[kb + c0 + j];

        float alpha[4];
#pragma unroll
        for (int i = 0; i < 4; i++) {
            float lm = -INFINITY;
#pragma unroll
            for (int j = 0; j < 4; j++) {
                s[i][j] = (s[i][j] + mk[j]) * 0.125f;
                lm = fmaxf(lm, s[i][j]);
            }
            lm = fmaxf(lm, __shfl_xor_sync(0xffffffffu, lm, 8));
            lm = fmaxf(lm, __shfl_xor_sync(0xffffffffu, lm, 4));
            lm = fmaxf(lm, __shfl_xor_sync(0xffffffffu, lm, 2));
            lm = fmaxf(lm, __shfl_xor_sync(0xffffffffu, lm, 1));
            float mn = fmaxf(m_i[i], lm);
            alpha[i] = __expf(m_i[i] - mn);
            m_i[i] = mn;
            float rs = 0.f;
#pragma unroll
            for (int j = 0; j < 4; j++) {
                s[i][j] = __expf(s[i][j] - mn);
                rs += s[i][j];
            }
            rs += __shfl_xor_sync(0xffffffffu, rs, 8);
            rs += __shfl_xor_sync(0xffffffffu, rs, 4);
            rs += __shfl_xor_sync(0xffffffffu, rs, 2);
            rs += __shfl_xor_sync(0xffffffffu, rs, 1);
            l_i[i] = l_i[i] * alpha[i] + rs;
        }

        __syncthreads();   // all threads done reading K from KP

        // ---- Write P (row-major, plain indexing) + rescale O ----
#pragma unroll
        for (int i = 0; i < 4; i++) {
#pragma unroll
            for (int j = 0; j < 4; j++)
                KP[(r0 + i) * 64 + c0 + j] = s[i][j];
#pragma unroll
            for (int j = 0; j < 4; j++)
                o[i][j] *= alpha[i];
        }
        __syncthreads();

        // ---- O += P @ V ----
#pragma unroll 8
        for (int kk = 0; kk < 64; kk++) {
            float4 v4 = *(const float4*)&Vs[kk * 64 + c0];
            float vv[4] = {v4.x, v4.y, v4.z, v4.w};
#pragma unroll
            for (int i = 0; i < 4; i++) {
                float p = KP[(r0 + i) * 64 + kk];
#pragma unroll
                for (int j = 0; j < 4; j++)
                    o[i][j] += p * vv[j];
            }
        }
    }

    // ---- Epilogue: normalize, write av[b, q, h, d] ----
#pragma unroll
    for (int i = 0; i < 4; i++) {
        float inv = 1.0f / l_i[i];
        float4 out4;
        out4.x = o[i][0] * inv;
        out4.y = o[i][1] * inv;
        out4.z = o[i][2] * inv;
        out4.w = o[i][3] * inv;
        *(float4*)(av + (size_t)(b * Sv + q0 + r0 + i) * Hv + h * HDv + c0) = out4;
    }
}

// ============================================================================
// Launch
// ============================================================================
extern "C" void kernel_launch(void* const* d_in, const int* in_sizes, int n_in,
                              void* d_out, int out_size)
{
    const float* x     = (const float*)d_in[0];
    const float* mask  = (const float*)d_in[1];
    const float* w_qkv = (const float*)d_in[2];
    const float* b_qkv = (const float*)d_in[3];
    const float* w_o   = (const float*)d_in[4];
    const float* b_o   = (const float*)d_in[5];
    float* out = (float*)d_out;

    float *p_qkv = nullptr, *p_av = nullptr;
    cudaGetSymbolAddress((void**)&p_qkv, g_qkv);
    cudaGetSymbolAddress((void**)&p_av, g_av);

    // 1) QKV projection: [4096,1024] x [3072,1024]^T -> [4096,3072]
    dim3 g1(H3 / BN, MSEQ / BM);
    gemm_nt_bias<<<g1, 256>>>(x, w_qkv, b_qkv, p_qkv, MSEQ, H3, Hv);

    // 2) Flash attention -> av [4096,1024] (bqhd layout)
    attn_kernel<<<dim3(Sv / 64, NHv, Bv), 256>>>(p_qkv, mask, p_av);

    // 3) Output projection: [4096,1024] x [1024,1024]^T -> out
    dim3 g2(Hv / BN, MSEQ / BM);
    gemm_nt_bias<<<g2, 256>>>(p_av, w_o, b_o, out, MSEQ, Hv, Hv);
}

// round 4
// speedup vs baseline: 1.2523x; 1.2523x over previous
#include <cuda_runtime.h>
#include <cuda_bf16.h>
#include <math.h>
#include <stdint.h>

// Problem constants
#define Bv   2
#define Sv   2048
#define Hv   1024
#define NHv  16
#define HDv  64
#define H3   (3 * Hv)
#define MSEQ (Bv * Sv)          // 4096 rows

// Scratch (device globals: allocation-guard safe)
__device__ float g_qkv[(size_t)MSEQ * H3];   // [B*S, 3H]
__device__ float g_av [(size_t)MSEQ * Hv];   // [B*S, H]

// ============================================================================
// Helpers
// ============================================================================
__device__ __forceinline__ uint32_t smem_to_u32(const void* smem_ptr) {
    uint32_t addr;
    asm("{ .reg .u64 tmp; cvta.to.shared.u64 tmp, %1; cvt.u32.u64 %0, tmp; }"
        : "=r"(addr) : "l"(smem_ptr));
    return addr;
}

__device__ __forceinline__ void ldsm_x4(uint32_t addr, uint32_t r[4]) {
    asm volatile("ldmatrix.sync.aligned.m8n8.x4.shared.b16 {%0,%1,%2,%3}, [%4];"
        : "=r"(r[0]), "=r"(r[1]), "=r"(r[2]), "=r"(r[3]) : "r"(addr));
}

__device__ __forceinline__ void mma_bf16(float d[4], const uint32_t a[4],
                                         uint32_t b0, uint32_t b1) {
    asm volatile(
        "mma.sync.aligned.m16n8k16.row.col.f32.bf16.bf16.f32 "
        "{%0,%1,%2,%3}, {%4,%5,%6,%7}, {%8,%9}, {%0,%1,%2,%3};"
        : "+f"(d[0]), "+f"(d[1]), "+f"(d[2]), "+f"(d[3])
        : "r"(a[0]), "r"(a[1]), "r"(a[2]), "r"(a[3]), "r"(b0), "r"(b1));
}

// Split a float into bf16 hi + bf16 lo (x ≈ hi + lo, residual ~2^-17 |x|)
__device__ __forceinline__ void split1(float x, uint16_t& h, uint16_t& l) {
    __nv_bfloat16 hb = __float2bfloat16_rn(x);
    float r = x - __bfloat162float(hb);
    __nv_bfloat16 lb = __float2bfloat16_rn(r);
    h = *(uint16_t*)&hb;
    l = *(uint16_t*)&lb;
}

__device__ __forceinline__ void split2(float x, float y, uint32_t& hi, uint32_t& lo) {
    uint16_t hx, lx, hy, ly;
    split1(x, hx, lx);
    split1(y, hy, ly);
    hi = (uint32_t)hx | ((uint32_t)hy << 16);
    lo = (uint32_t)lx | ((uint32_t)ly << 16);
}

__device__ __forceinline__ void split8(const float4& u, const float4& v,
                                       uint4& hi, uint4& lo) {
    split2(u.x, u.y, hi.x, lo.x);
    split2(u.z, u.w, hi.y, lo.y);
    split2(v.x, v.y, hi.z, lo.z);
    split2(v.z, v.w, hi.w, lo.w);
}

// ============================================================================
// bf16x3 tensor-core GEMM (NT): C[m,n] = sum_k A[m,k]*W[n,k] + bias[n]
// CTA tile 128x128, K-chunk 32. 8 warps (4m x 2n), warp tile 32x64.
// SMEM: k-major tiles, row stride 40 bf16 (80 B) -> conflict-free ldmatrix.
// Both A and B fragments load via NON-trans ldmatrix (k-major NT layout).
// 3 passes per k-step: A_hi*B_hi + A_lo*B_hi + A_hi*B_lo  (error ~1e-5)
// ============================================================================
#define SRB   80                 // smem row stride bytes (40 bf16)
#define MATB  (128 * SRB)        // one 128x32 bf16 matrix: 10240 B
#define BUFB  (4 * MATB)         // Ahi, Alo, Whi, Wlo: 40960 B
#define GSM_TOTAL (2 * BUFB)     // double buffered: 81920 B

__global__ __launch_bounds__(256)
void gemm_mma_bf16x3(const float* __restrict__ A, const float* __restrict__ W,
                     const float* __restrict__ bias, float* __restrict__ C,
                     int M, int N, int K)
{
    extern __shared__ char smem[];
    const uint32_t smb = smem_to_u32(smem);
    const int tid = threadIdx.x;
    const int lid = tid & 31;
    const int wid = tid >> 5;
    const int wm  = wid & 3;          // m-warp: 0..3 (x32 rows)
    const int wn  = wid >> 2;         // n-warp: 0..1 (x64 cols)
    const int m0  = blockIdx.y * 128;
    const int n0  = blockIdx.x * 128;

    // ---- gmem load mapping: thread -> (row tid>>1, k-half (tid&1)*16) ----
    const int lrow = tid >> 1;
    const int lkp  = (tid & 1) * 16;
    const float* ga = A + (size_t)(m0 + lrow) * K + lkp;
    const float* gw = W + (size_t)(n0 + lrow) * K + lkp;
    const uint32_t stoff = (uint32_t)(lrow * SRB + lkp * 2);

    float4 ra[4], rw[4];   // prefetch registers (chunk of 32 k for A-row & W-row)

    // ---- ldmatrix per-thread offsets (identical scheme for A and B) ----
    // lanes 0-7: rows 0-7 k-lo | 8-15: rows 8-15 k-lo | 16-23: rows 0-7 k-hi | 24-31: rows 8-15 k-hi
    const uint32_t aoff = (uint32_t)((wm * 32 + (lid & 7) + ((lid >> 3) & 1) * 8) * SRB
                                     + (lid >> 4) * 16);
    // B: lanes 0-7: n0-7 k-lo | 8-15: n0-7 k-hi | 16-23: n8-15 k-lo | 24-31: n8-15 k-hi
    const uint32_t boff = (uint32_t)((wn * 64 + (lid & 7) + (lid >> 4) * 8) * SRB
                                     + ((lid >> 3) & 1) * 16);

    float acc[2][8][4];
#pragma unroll
    for (int i = 0; i < 2; i++)
#pragma unroll
        for (int j = 0; j < 8; j++)
#pragma unroll
            for (int e = 0; e < 4; e++) acc[i][j][e] = 0.f;

    auto LDG = [&](int k0) {
        ra[0] = *(const float4*)(ga + k0);
        ra[1] = *(const float4*)(ga + k0 + 4);
        ra[2] = *(const float4*)(ga + k0 + 8);
        ra[3] = *(const float4*)(ga + k0 + 12);
        rw[0] = *(const float4*)(gw + k0);
        rw[1] = *(const float4*)(gw + k0 + 4);
        rw[2] = *(const float4*)(gw + k0 + 8);
        rw[3] = *(const float4*)(gw + k0 + 12);
    };

    auto STS = [&](int buf) {
        char* base = smem + buf * BUFB;
#pragma unroll
        for (int g = 0; g < 2; g++) {
            uint4 hi, lo;
            split8(ra[2 * g], ra[2 * g + 1], hi, lo);
            *(uint4*)(base + stoff + g * 16)        = hi;   // A_hi
            *(uint4*)(base + MATB + stoff + g * 16) = lo;   // A_lo
            split8(rw[2 * g], rw[2 * g + 1], hi, lo);
            *(uint4*)(base + 2 * MATB + stoff + g * 16) = hi;  // W_hi
            *(uint4*)(base + 3 * MATB + stoff + g * 16) = lo;  // W_lo
        }
    };

    auto MMA = [&](int buf) {
        const uint32_t base = smb + buf * BUFB;
#pragma unroll
        for (int kt = 0; kt < 2; kt++) {
#pragma unroll
            for (int pass = 0; pass < 3; pass++) {
                const uint32_t abase = base + (pass == 1 ? MATB : 0u);
                const uint32_t bbase = base + 2u * MATB + (pass == 2 ? MATB : 0u);
                uint32_t a0[4], a1[4];
                ldsm_x4(abase + aoff + kt * 32, a0);
                ldsm_x4(abase + aoff + 16 * SRB + kt * 32, a1);
#pragma unroll
                for (int gn = 0; gn < 4; gn++) {
                    uint32_t bb[4];
                    ldsm_x4(bbase + boff + gn * (16 * SRB) + kt * 32, bb);
                    mma_bf16(acc[0][2 * gn],     a0, bb[0], bb[1]);
                    mma_bf16(acc[0][2 * gn + 1], a0, bb[2], bb[3]);
                    mma_bf16(acc[1][2 * gn],     a1, bb[0], bb[1]);
                    mma_bf16(acc[1][2 * gn + 1], a1, bb[2], bb[3]);
                }
            }
        }
    };

    const int NCHUNK = K / 32;
    LDG(0);
    STS(0);
    __syncthreads();

    for (int i = 0; i < NCHUNK; i++) {
        if (i + 1 < NCHUNK) LDG((i + 1) * 32);
        MMA(i & 1);
        if (i + 1 < NCHUNK) {
            __syncthreads();
            STS((i + 1) & 1);
            __syncthreads();
        }
    }

    // ---- Epilogue: acc -> C (+bias) ----
#pragma unroll
    for (int mt = 0; mt < 2; mt++) {
        const int row = m0 + wm * 32 + mt * 16 + (lid >> 2);
#pragma unroll
        for (int nt = 0; nt < 8; nt++) {
            const int col = n0 + wn * 64 + nt * 8 + (lid & 3) * 2;
            const float b0 = bias[col], b1 = bias[col + 1];
            float2 v0 = {acc[mt][nt][0] + b0, acc[mt][nt][1] + b1};
            float2 v1 = {acc[mt][nt][2] + b0, acc[mt][nt][3] + b1};
            *(float2*)(C + (size_t)row * N + col)       = v0;
            *(float2*)(C + (size_t)(row + 8) * N + col) = v1;
        }
    }
}

// ============================================================================
// Flash attention, fp32 (unchanged — passed R1)
// ============================================================================
__global__ __launch_bounds__(256)
void attn_kernel(const float* __restrict__ qkv, const float* __restrict__ mask,
                 float* __restrict__ av)
{
    __shared__ float Qs[HDv * 64];
    __shared__ float KP[HDv * 64];
    __shared__ float Vs[64 * HDv];

    const int tid = threadIdx.x;
    const int tx  = tid & 15;
    const int ty  = tid >> 4;
    const int q0  = blockIdx.x * 64;
    const int h   = blockIdx.y;
    const int b   = blockIdx.z;
    const int r0  = ty * 4;
    const int c0  = tx * 4;
    const size_t base = (size_t)b * Sv * H3 + (size_t)h * HDv;

#pragma unroll
    for (int l = 0; l < 4; l++) {
        int idx = tid + l * 256;
        int r   = idx >> 4;
        int dv  = (idx & 15) << 2;
        float4 v = *(const float4*)(qkv + base + (size_t)(q0 + r) * H3 + dv);
        float vv[4] = {v.x, v.y, v.z, v.w};
#pragma unroll
        for (int e = 0; e < 4; e++) {
            int d = dv + e;
            Qs[d * 64 + ((((r >> 2) ^ (d & 15)) << 2) | (r & 3))] = vv[e];
        }
    }

    float m_i[4], l_i[4], o[4][4];
#pragma unroll
    for (int i = 0; i < 4; i++) {
        m_i[i] = -INFINITY; l_i[i] = 0.f;
#pragma unroll
        for (int j = 0; j < 4; j++) o[i][j] = 0.f;
    }

    for (int kt = 0; kt < Sv / 64; kt++) {
        const int kb = kt * 64;
        __syncthreads();

#pragma unroll
        for (int l = 0; l < 4; l++) {
            int idx = tid + l * 256;
            int r   = idx >> 4;
            int dv  = (idx & 15) << 2;
            const float* kp = qkv + base + (size_t)(kb + r) * H3 + Hv + dv;
            float4 k4 = *(const float4*)kp;
            float kvv[4] = {k4.x, k4.y, k4.z, k4.w};
#pragma unroll
            for (int e = 0; e < 4; e++) {
                int d = dv + e;
                KP[d * 64 + ((((r >> 2) ^ (d & 15)) << 2) | (r & 3))] = kvv[e];
            }
            float4 v4 = *(const float4*)(kp + Hv);
            *(float4*)&Vs[r * 64 + dv] = v4;
        }
        __syncthreads();

        float s[4][4];
#pragma unroll
        for (int i = 0; i < 4; i++)
#pragma unroll
            for (int j = 0; j < 4; j++) s[i][j] = 0.f;

#pragma unroll 16
        for (int d = 0; d < HDv; d++) {
            float4 qa = *(const float4*)&Qs[d * 64 + ((ty ^ (d & 15)) << 2)];
            float4 ka = *(const float4*)&KP[d * 64 + ((tx ^ (d & 15)) << 2)];
            float qs[4] = {qa.x, qa.y, qa.z, qa.w};
            float ks[4] = {ka.x, ka.y, ka.z, ka.w};
#pragma unroll
            for (int i = 0; i < 4; i++)
#pragma unroll
                for (int j = 0; j < 4; j++)
                    s[i][j] += qs[i] * ks[j];
        }

        float mk[4];
#pragma unroll
        for (int j = 0; j < 4; j++) mk[j] = mask[kb + c0 + j];

        float alpha[4];
#pragma unroll
        for (int i = 0; i < 4; i++) {
            float lm = -INFINITY;
#pragma unroll
            for (int j = 0; j < 4; j++) {
                s[i][j] = (s[i][j] + mk[j]) * 0.125f;
                lm = fmaxf(lm, s[i][j]);
            }
            lm = fmaxf(lm, __shfl_xor_sync(0xffffffffu, lm, 8));
            lm = fmaxf(lm, __shfl_xor_sync(0xffffffffu, lm, 4));
            lm = fmaxf(lm, __shfl_xor_sync(0xffffffffu, lm, 2));
            lm = fmaxf(lm, __shfl_xor_sync(0xffffffffu, lm, 1));
            float mn = fmaxf(m_i[i], lm);
            alpha[i] = __expf(m_i[i] - mn);
            m_i[i] = mn;
            float rs = 0.f;
#pragma unroll
            for (int j = 0; j < 4; j++) {
                s[i][j] = __expf(s[i][j] - mn);
                rs += s[i][j];
            }
            rs += __shfl_xor_sync(0xffffffffu, rs, 8);
            rs += __shfl_xor_sync(0xffffffffu, rs, 4);
            rs += __shfl_xor_sync(0xffffffffu, rs, 2);
            rs += __shfl_xor_sync(0xffffffffu, rs, 1);
            l_i[i] = l_i[i] * alpha[i] + rs;
        }

        __syncthreads();

#pragma unroll
        for (int i = 0; i < 4; i++) {
#pragma unroll
            for (int j = 0; j < 4; j++)
                KP[(r0 + i) * 64 + c0 + j] = s[i][j];
#pragma unroll
            for (int j = 0; j < 4; j++)
                o[i][j] *= alpha[i];
        }
        __syncthreads();

#pragma unroll 8
        for (int kk = 0; kk < 64; kk++) {
            float4 v4 = *(const float4*)&Vs[kk * 64 + c0];
            float vv[4] = {v4.x, v4.y, v4.z, v4.w};
#pragma unroll
            for (int i = 0; i < 4; i++) {
                float p = KP[(r0 + i) * 64 + kk];
#pragma unroll
                for (int j = 0; j < 4; j++)
                    o[i][j] += p * vv[j];
            }
        }
    }

#pragma unroll
    for (int i = 0; i < 4; i++) {
        float inv = 1.0f / l_i[i];
        float4 out4;
        out4.x = o[i][0] * inv;
        out4.y = o[i][1] * inv;
        out4.z = o[i][2] * inv;
        out4.w = o[i][3] * inv;
        *(float4*)(av + (size_t)(b * Sv + q0 + r0 + i) * Hv + h * HDv + c0) = out4;
    }
}

// ============================================================================
// Launch
// ============================================================================
extern "C" void kernel_launch(void* const* d_in, const int* in_sizes, int n_in,
                              void* d_out, int out_size)
{
    const float* x     = (const float*)d_in[0];
    const float* mask  = (const float*)d_in[1];
    const float* w_qkv = (const float*)d_in[2];
    const float* b_qkv = (const float*)d_in[3];
    const float* w_o   = (const float*)d_in[4];
    const float* b_o   = (const float*)d_in[5];
    float* out = (float*)d_out;

    float *p_qkv = nullptr, *p_av = nullptr;
    cudaGetSymbolAddress((void**)&p_qkv, g_qkv);
    cudaGetSymbolAddress((void**)&p_av, g_av);

    cudaFuncSetAttribute(gemm_mma_bf16x3,
                         cudaFuncAttributeMaxDynamicSharedMemorySize, GSM_TOTAL);

    // 1) QKV projection: [4096,1024] x [3072,1024]^T -> [4096,3072]
    dim3 g1(H3 / 128, MSEQ / 128);
    gemm_mma_bf16x3<<<g1, 256, GSM_TOTAL>>>(x, w_qkv, b_qkv, p_qkv, MSEQ, H3, Hv);

    // 2) Flash attention -> av [4096,1024] (bqhd layout)
    attn_kernel<<<dim3(Sv / 64, NHv, Bv), 256>>>(p_qkv, mask, p_av);

    // 3) Output projection: [4096,1024] x [1024,1024]^T -> out
    dim3 g2(Hv / 128, MSEQ / 128);
    gemm_mma_bf16x3<<<g2, 256, GSM_TOTAL>>>(p_av, w_o, b_o, out, MSEQ, Hv, Hv);
}

// round 5
// speedup vs baseline: 2.1976x; 1.7548x over previous
#include <cuda_runtime.h>
#include <cuda_bf16.h>
#include <math.h>
#include <stdint.h>

// Problem constants
#define Bv   2
#define Sv   2048
#define Hv   1024
#define NHv  16
#define HDv  64
#define H3   (3 * Hv)
#define MSEQ (Bv * Sv)          // 4096 rows

// Scratch (device globals: allocation-guard safe)
__device__ __nv_bfloat16 g_qkvh[(size_t)MSEQ * H3];  // qkv hi bf16
__device__ __nv_bfloat16 g_qkvl[(size_t)MSEQ * H3];  // qkv lo bf16
__device__ float g_av[(size_t)MSEQ * Hv];            // attention out fp32

// ============================================================================
// Helpers
// ============================================================================
__device__ __forceinline__ uint32_t smem_to_u32(const void* smem_ptr) {
    uint32_t addr;
    asm("{ .reg .u64 tmp; cvta.to.shared.u64 tmp, %1; cvt.u32.u64 %0, tmp; }"
        : "=r"(addr) : "l"(smem_ptr));
    return addr;
}

__device__ __forceinline__ void ldsm_x4(uint32_t addr, uint32_t r[4]) {
    asm volatile("ldmatrix.sync.aligned.m8n8.x4.shared.b16 {%0,%1,%2,%3}, [%4];"
        : "=r"(r[0]), "=r"(r[1]), "=r"(r[2]), "=r"(r[3]) : "r"(addr));
}

__device__ __forceinline__ void ldsm_x4_t(uint32_t addr, uint32_t r[4]) {
    asm volatile("ldmatrix.sync.aligned.m8n8.x4.trans.shared.b16 {%0,%1,%2,%3}, [%4];"
        : "=r"(r[0]), "=r"(r[1]), "=r"(r[2]), "=r"(r[3]) : "r"(addr));
}

__device__ __forceinline__ void mma_bf16(float d[4], const uint32_t a[4],
                                         uint32_t b0, uint32_t b1) {
    asm volatile(
        "mma.sync.aligned.m16n8k16.row.col.f32.bf16.bf16.f32 "
        "{%0,%1,%2,%3}, {%4,%5,%6,%7}, {%8,%9}, {%0,%1,%2,%3};"
        : "+f"(d[0]), "+f"(d[1]), "+f"(d[2]), "+f"(d[3])
        : "r"(a[0]), "r"(a[1]), "r"(a[2]), "r"(a[3]), "r"(b0), "r"(b1));
}

// Split a float into bf16 hi + bf16 lo (x ≈ hi + lo, residual ~2^-17 |x|)
__device__ __forceinline__ void split1(float x, uint16_t& h, uint16_t& l) {
    __nv_bfloat16 hb = __float2bfloat16_rn(x);
    float r = x - __bfloat162float(hb);
    __nv_bfloat16 lb = __float2bfloat16_rn(r);
    h = *(uint16_t*)&hb;
    l = *(uint16_t*)&lb;
}

__device__ __forceinline__ void split2(float x, float y, uint32_t& hi, uint32_t& lo) {
    uint16_t hx, lx, hy, ly;
    split1(x, hx, lx);
    split1(y, hy, ly);
    hi = (uint32_t)hx | ((uint32_t)hy << 16);
    lo = (uint32_t)lx | ((uint32_t)ly << 16);
}

__device__ __forceinline__ void split8(const float4& u, const float4& v,
                                       uint4& hi, uint4& lo) {
    split2(u.x, u.y, hi.x, lo.x);
    split2(u.z, u.w, hi.y, lo.y);
    split2(v.x, v.y, hi.z, lo.z);
    split2(v.z, v.w, hi.w, lo.w);
}

#define CP_ASYNC16(dst_u32, src_ptr) \
    asm volatile("cp.async.cg.shared.global [%0], [%1], 16;" \
        :: "r"(dst_u32), "l"(src_ptr))
#define CP_ASYNC_COMMIT() asm volatile("cp.async.commit_group;" ::: "memory")
#define CP_ASYNC_WAIT(N)  asm volatile("cp.async.wait_group %0;" :: "n"(N) : "memory")

// ============================================================================
// bf16x3 tensor-core GEMM (NT): C[m,n] = sum_k A[m,k]*W[n,k] + bias[n]
// OUT_SPLIT=1: write bf16 hi/lo pair arrays; OUT_SPLIT=0: write fp32 C.
// ============================================================================
#define SRB   80                 // smem row stride bytes (40 bf16)
#define MATB  (128 * SRB)        // one 128x32 bf16 matrix: 10240 B
#define BUFB  (4 * MATB)         // Ahi, Alo, Whi, Wlo: 40960 B
#define GSM_TOTAL (2 * BUFB)     // double buffered: 81920 B

template<int OUT_SPLIT>
__global__ __launch_bounds__(256)
void gemm_mma_bf16x3(const float* __restrict__ A, const float* __restrict__ W,
                     const float* __restrict__ bias, float* __restrict__ C,
                     __nv_bfloat16* __restrict__ Ch, __nv_bfloat16* __restrict__ Cl,
                     int M, int N, int K)
{
    extern __shared__ char smem[];
    const uint32_t smb = smem_to_u32(smem);
    const int tid = threadIdx.x;
    const int lid = tid & 31;
    const int wid = tid >> 5;
    const int wm  = wid & 3;
    const int wn  = wid >> 2;
    const int m0  = blockIdx.y * 128;
    const int n0  = blockIdx.x * 128;

    const int lrow = tid >> 1;
    const int lkp  = (tid & 1) * 16;
    const float* ga = A + (size_t)(m0 + lrow) * K + lkp;
    const float* gw = W + (size_t)(n0 + lrow) * K + lkp;
    const uint32_t stoff = (uint32_t)(lrow * SRB + lkp * 2);

    float4 ra[4], rw[4];

    const uint32_t aoff = (uint32_t)((wm * 32 + (lid & 7) + ((lid >> 3) & 1) * 8) * SRB
                                     + (lid >> 4) * 16);
    const uint32_t boff = (uint32_t)((wn * 64 + (lid & 7) + (lid >> 4) * 8) * SRB
                                     + ((lid >> 3) & 1) * 16);

    float acc[2][8][4];
#pragma unroll
    for (int i = 0; i < 2; i++)
#pragma unroll
        for (int j = 0; j < 8; j++)
#pragma unroll
            for (int e = 0; e < 4; e++) acc[i][j][e] = 0.f;

    auto LDG = [&](int k0) {
        ra[0] = *(const float4*)(ga + k0);
        ra[1] = *(const float4*)(ga + k0 + 4);
        ra[2] = *(const float4*)(ga + k0 + 8);
        ra[3] = *(const float4*)(ga + k0 + 12);
        rw[0] = *(const float4*)(gw + k0);
        rw[1] = *(const float4*)(gw + k0 + 4);
        rw[2] = *(const float4*)(gw + k0 + 8);
        rw[3] = *(const float4*)(gw + k0 + 12);
    };

    auto STS = [&](int buf) {
        char* base = smem + buf * BUFB;
#pragma unroll
        for (int g = 0; g < 2; g++) {
            uint4 hi, lo;
            split8(ra[2 * g], ra[2 * g + 1], hi, lo);
            *(uint4*)(base + stoff + g * 16)        = hi;
            *(uint4*)(base + MATB + stoff + g * 16) = lo;
            split8(rw[2 * g], rw[2 * g + 1], hi, lo);
            *(uint4*)(base + 2 * MATB + stoff + g * 16) = hi;
            *(uint4*)(base + 3 * MATB + stoff + g * 16) = lo;
        }
    };

    auto MMA = [&](int buf) {
        const uint32_t base = smb + buf * BUFB;
#pragma unroll
        for (int kt = 0; kt < 2; kt++) {
#pragma unroll
            for (int pass = 0; pass < 3; pass++) {
                const uint32_t abase = base + (pass == 1 ? MATB : 0u);
                const uint32_t bbase = base + 2u * MATB + (pass == 2 ? MATB : 0u);
                uint32_t a0[4], a1[4];
                ldsm_x4(abase + aoff + kt * 32, a0);
                ldsm_x4(abase + aoff + 16 * SRB + kt * 32, a1);
#pragma unroll
                for (int gn = 0; gn < 4; gn++) {
                    uint32_t bb[4];
                    ldsm_x4(bbase + boff + gn * (16 * SRB) + kt * 32, bb);
                    mma_bf16(acc[0][2 * gn],     a0, bb[0], bb[1]);
                    mma_bf16(acc[0][2 * gn + 1], a0, bb[2], bb[3]);
                    mma_bf16(acc[1][2 * gn],     a1, bb[0], bb[1]);
                    mma_bf16(acc[1][2 * gn + 1], a1, bb[2], bb[3]);
                }
            }
        }
    };

    const int NCHUNK = K / 32;
    LDG(0);
    STS(0);
    __syncthreads();

    for (int i = 0; i < NCHUNK; i++) {
        if (i + 1 < NCHUNK) LDG((i + 1) * 32);
        MMA(i & 1);
        if (i + 1 < NCHUNK) {
            __syncthreads();
            STS((i + 1) & 1);
            __syncthreads();
        }
    }

    // ---- Epilogue ----
#pragma unroll
    for (int mt = 0; mt < 2; mt++) {
        const int row = m0 + wm * 32 + mt * 16 + (lid >> 2);
#pragma unroll
        for (int nt = 0; nt < 8; nt++) {
            const int col = n0 + wn * 64 + nt * 8 + (lid & 3) * 2;
            const float b0 = bias[col], b1 = bias[col + 1];
            float v00 = acc[mt][nt][0] + b0, v01 = acc[mt][nt][1] + b1;
            float v10 = acc[mt][nt][2] + b0, v11 = acc[mt][nt][3] + b1;
            if (OUT_SPLIT) {
                uint32_t h0, l0, h1, l1;
                split2(v00, v01, h0, l0);
                split2(v10, v11, h1, l1);
                *(uint32_t*)(Ch + (size_t)row * N + col)       = h0;
                *(uint32_t*)(Cl + (size_t)row * N + col)       = l0;
                *(uint32_t*)(Ch + (size_t)(row + 8) * N + col) = h1;
                *(uint32_t*)(Cl + (size_t)(row + 8) * N + col) = l1;
            } else {
                *(float2*)(C + (size_t)row * N + col)       = make_float2(v00, v01);
                *(float2*)(C + (size_t)(row + 8) * N + col) = make_float2(v10, v11);
            }
        }
    }
}

// ============================================================================
// Tensor-core flash attention (bf16x3).
// CTA: 128 q-rows x one (b,h). 8 warps x 16 q-rows. K-tile = 64 keys.
// Tiles in smem with 144B row stride (conflict-free ldmatrix), double-buffered
// K/V via cp.async. Online softmax in fragments; P repacked reg->reg.
// ============================================================================
#define SRA   144                 // bf16 tile row stride bytes (72 bf16)
#define QTB   (128 * SRA)         // 18432
#define KVTB  (64 * SRA)          // 9216
#define AS_QH 0
#define AS_QL QTB
#define AS_KV (2 * QTB)                    // 36864
#define AS_MS (AS_KV + 2 * 4 * KVTB)       // 110592
#define ATT_SMEM (AS_MS + Sv * 4)          // +8192 = 118784

__global__ __launch_bounds__(256)
void attn_mma(const __nv_bfloat16* __restrict__ qh,
              const __nv_bfloat16* __restrict__ ql,
              const float* __restrict__ mask, float* __restrict__ av)
{
    extern __shared__ char smem[];
    const uint32_t smb = smem_to_u32(smem);
    const int tid = threadIdx.x;
    const int lid = tid & 31;
    const int wq  = tid >> 5;           // 0..7 -> 16-row group
    const int q0  = blockIdx.x * 128;
    const int h   = blockIdx.y;
    const int b   = blockIdx.z;
    const size_t rowbase = (size_t)b * Sv;
    const int hd0 = h * HDv;

    // ---- preload: mask + Q(hi/lo) + KV tile 0, one cp.async group ----
#pragma unroll
    for (int i = 0; i < 2; i++) {
        int idx = tid + i * 256;
        CP_ASYNC16(smb + AS_MS + idx * 16, mask + idx * 4);
    }
#pragma unroll
    for (int i = 0; i < 8; i++) {
        int idx = tid + i * 256;
        int mat = idx >> 10, rem = idx & 1023;
        int r = rem >> 3, c = rem & 7;
        const __nv_bfloat16* src = (mat ? ql : qh)
            + (rowbase + q0 + r) * H3 + hd0 + c * 8;
        CP_ASYNC16(smb + (mat ? AS_QL : AS_QH) + r * SRA + c * 16, src);
    }
#pragma unroll
    for (int i = 0; i < 8; i++) {
        int idx = tid + i * 256;
        int mat = idx >> 9, rem = idx & 511;
        int r = rem >> 3, c = rem & 7;
        const __nv_bfloat16* base = (mat & 1) ? ql : qh;
        int off = (mat >> 1) ? 2 * Hv : Hv;   // K at +Hv, V at +2Hv
        CP_ASYNC16(smb + AS_KV + mat * KVTB + r * SRA + c * 16,
                   base + (rowbase + r) * H3 + off + hd0 + c * 8);
    }
    CP_ASYNC_COMMIT();

    // Fragment address bases
    const uint32_t aoffQ = (uint32_t)((wq * 16 + (lid & 7) + ((lid >> 3) & 1) * 8) * SRA
                                      + (lid >> 4) * 16);
    const uint32_t boffK = (uint32_t)(((lid & 7) + (lid >> 4) * 8) * SRA
                                      + ((lid >> 3) & 1) * 16);
    const uint32_t voffV = (uint32_t)(((lid & 7) + ((lid >> 3) & 1) * 8) * SRA
                                      + (lid >> 4) * 16);

    float o[8][4];
#pragma unroll
    for (int j = 0; j < 8; j++)
#pragma unroll
        for (int e = 0; e < 4; e++) o[j][e] = 0.f;
    float m0 = -INFINITY, m1 = -INFINITY, l0 = 0.f, l1 = 0.f;

    const int NT = Sv / 64;   // 32 tiles
    for (int t = 0; t < NT; t++) {
        __syncthreads();      // all warps done with previous compute
        if (t + 1 < NT) {
            const int kb = (t + 1) * 64;
            const uint32_t kvb = smb + AS_KV + ((t + 1) & 1) * (4 * KVTB);
#pragma unroll
            for (int i = 0; i < 8; i++) {
                int idx = tid + i * 256;
                int mat = idx >> 9, rem = idx & 511;
                int r = rem >> 3, c = rem & 7;
                const __nv_bfloat16* base = (mat & 1) ? ql : qh;
                int off = (mat >> 1) ? 2 * Hv : Hv;
                CP_ASYNC16(kvb + mat * KVTB + r * SRA + c * 16,
                           base + (rowbase + kb + r) * H3 + off + hd0 + c * 8);
            }
            CP_ASYNC_COMMIT();
            CP_ASYNC_WAIT(1);
        } else {
            CP_ASYNC_WAIT(0);
        }
        __syncthreads();

        const uint32_t kvb = smb + AS_KV + (t & 1) * (4 * KVTB);
        const uint32_t KH = kvb, KL = kvb + KVTB, VH = kvb + 2 * KVTB, VL = kvb + 3 * KVTB;

        // ---- S = Q K^T (bf16x3) ----
        float s[8][4];
#pragma unroll
        for (int j = 0; j < 8; j++)
#pragma unroll
            for (int e = 0; e < 4; e++) s[j][e] = 0.f;

#pragma unroll
        for (int kt = 0; kt < 4; kt++) {
            uint32_t aQh[4], aQl[4];
            ldsm_x4(smb + AS_QH + aoffQ + kt * 32, aQh);
            ldsm_x4(smb + AS_QL + aoffQ + kt * 32, aQl);
#pragma unroll
            for (int gn = 0; gn < 4; gn++) {
                uint32_t bh[4], bl[4];
                ldsm_x4(KH + boffK + gn * (16 * SRA) + kt * 32, bh);
                ldsm_x4(KL + boffK + gn * (16 * SRA) + kt * 32, bl);
                mma_bf16(s[2 * gn],     aQh, bh[0], bh[1]);
                mma_bf16(s[2 * gn + 1], aQh, bh[2], bh[3]);
                mma_bf16(s[2 * gn],     aQl, bh[0], bh[1]);
                mma_bf16(s[2 * gn + 1], aQl, bh[2], bh[3]);
                mma_bf16(s[2 * gn],     aQh, bl[0], bl[1]);
                mma_bf16(s[2 * gn + 1], aQh, bl[2], bl[3]);
            }
        }

        // ---- online softmax ----
        const uint32_t msb = smb + AS_MS + (uint32_t)((t * 64 + 2 * (lid & 3)) * 4);
        float tm0 = -INFINITY, tm1 = -INFINITY;
#pragma unroll
        for (int j = 0; j < 8; j++) {
            float mkx, mky;
            asm("ld.shared.v2.f32 {%0,%1}, [%2];" : "=f"(mkx), "=f"(mky) : "r"(msb + j * 32));
            s[j][0] = (s[j][0] + mkx) * 0.125f;
            s[j][1] = (s[j][1] + mky) * 0.125f;
            s[j][2] = (s[j][2] + mkx) * 0.125f;
            s[j][3] = (s[j][3] + mky) * 0.125f;
            tm0 = fmaxf(tm0, fmaxf(s[j][0], s[j][1]));
            tm1 = fmaxf(tm1, fmaxf(s[j][2], s[j][3]));
        }
        tm0 = fmaxf(tm0, __shfl_xor_sync(0xffffffffu, tm0, 1));
        tm0 = fmaxf(tm0, __shfl_xor_sync(0xffffffffu, tm0, 2));
        tm1 = fmaxf(tm1, __shfl_xor_sync(0xffffffffu, tm1, 1));
        tm1 = fmaxf(tm1, __shfl_xor_sync(0xffffffffu, tm1, 2));

        const float mn0 = fmaxf(m0, tm0), mn1 = fmaxf(m1, tm1);
        const float al0 = __expf(m0 - mn0), al1 = __expf(m1 - mn1);
        m0 = mn0; m1 = mn1;

        float rs0 = 0.f, rs1 = 0.f;
#pragma unroll
        for (int j = 0; j < 8; j++) {
            s[j][0] = __expf(s[j][0] - mn0);
            s[j][1] = __expf(s[j][1] - mn0);
            s[j][2] = __expf(s[j][2] - mn1);
            s[j][3] = __expf(s[j][3] - mn1);
            rs0 += s[j][0] + s[j][1];
            rs1 += s[j][2] + s[j][3];
        }
        rs0 += __shfl_xor_sync(0xffffffffu, rs0, 1);
        rs0 += __shfl_xor_sync(0xffffffffu, rs0, 2);
        rs1 += __shfl_xor_sync(0xffffffffu, rs1, 1);
        rs1 += __shfl_xor_sync(0xffffffffu, rs1, 2);
        l0 = l0 * al0 + rs0;
        l1 = l1 * al1 + rs1;

#pragma unroll
        for (int j = 0; j < 8; j++) {
            o[j][0] *= al0; o[j][1] *= al0;
            o[j][2] *= al1; o[j][3] *= al1;
        }

        // ---- O += P V (bf16x3) ----
#pragma unroll
        for (int kt = 0; kt < 4; kt++) {
            uint32_t ah[4], al_[4];
            split2(s[2 * kt][0],     s[2 * kt][1],     ah[0], al_[0]);
            split2(s[2 * kt][2],     s[2 * kt][3],     ah[1], al_[1]);
            split2(s[2 * kt + 1][0], s[2 * kt + 1][1], ah[2], al_[2]);
            split2(s[2 * kt + 1][2], s[2 * kt + 1][3], ah[3], al_[3]);
#pragma unroll
            for (int jp = 0; jp < 4; jp++) {
                uint32_t bh[4], bl[4];
                ldsm_x4_t(VH + voffV + kt * (16 * SRA) + jp * 32, bh);
                ldsm_x4_t(VL + voffV + kt * (16 * SRA) + jp * 32, bl);
                mma_bf16(o[2 * jp],     ah,  bh[0], bh[1]);
                mma_bf16(o[2 * jp + 1], ah,  bh[2], bh[3]);
                mma_bf16(o[2 * jp],     al_, bh[0], bh[1]);
                mma_bf16(o[2 * jp + 1], al_, bh[2], bh[3]);
                mma_bf16(o[2 * jp],     ah,  bl[0], bl[1]);
                mma_bf16(o[2 * jp + 1], ah,  bl[2], bl[3]);
            }
        }
    }

    // ---- Epilogue: normalize and store av[b, q, h*64 + d] ----
    const float inv0 = 1.f / l0, inv1 = 1.f / l1;
    const int rg = q0 + wq * 16 + (lid >> 2);
    float* outp = av + (rowbase + rg) * Hv + hd0 + 2 * (lid & 3);
#pragma unroll
    for (int j = 0; j < 8; j++) {
        *(float2*)(outp + j * 8)          = make_float2(o[j][0] * inv0, o[j][1] * inv0);
        *(float2*)(outp + 8 * Hv + j * 8) = make_float2(o[j][2] * inv1, o[j][3] * inv1);
    }
}

// ============================================================================
// Launch
// ============================================================================
extern "C" void kernel_launch(void* const* d_in, const int* in_sizes, int n_in,
                              void* d_out, int out_size)
{
    const float* x     = (const float*)d_in[0];
    const float* mask  = (const float*)d_in[1];
    const float* w_qkv = (const float*)d_in[2];
    const float* b_qkv = (const float*)d_in[3];
    const float* w_o   = (const float*)d_in[4];
    const float* b_o   = (const float*)d_in[5];
    float* out = (float*)d_out;

    __nv_bfloat16 *p_qkvh = nullptr, *p_qkvl = nullptr;
    float* p_av = nullptr;
    cudaGetSymbolAddress((void**)&p_qkvh, g_qkvh);
    cudaGetSymbolAddress((void**)&p_qkvl, g_qkvl);
    cudaGetSymbolAddress((void**)&p_av, g_av);

    cudaFuncSetAttribute(gemm_mma_bf16x3<1>,
                         cudaFuncAttributeMaxDynamicSharedMemorySize, GSM_TOTAL);
    cudaFuncSetAttribute(gemm_mma_bf16x3<0>,
                         cudaFuncAttributeMaxDynamicSharedMemorySize, GSM_TOTAL);
    cudaFuncSetAttribute(attn_mma,
                         cudaFuncAttributeMaxDynamicSharedMemorySize, ATT_SMEM);

    // 1) QKV projection -> split bf16 hi/lo
    dim3 g1(H3 / 128, MSEQ / 128);
    gemm_mma_bf16x3<1><<<g1, 256, GSM_TOTAL>>>(x, w_qkv, b_qkv, nullptr,
                                               p_qkvh, p_qkvl, MSEQ, H3, Hv);

    // 2) Tensor-core flash attention -> av fp32 [b*s][h*64+d]
    attn_mma<<<dim3(Sv / 128, NHv, Bv), 256, ATT_SMEM>>>(p_qkvh, p_qkvl, mask, p_av);

    // 3) Output projection -> out fp32
    dim3 g2(Hv / 128, MSEQ / 128);
    gemm_mma_bf16x3<0><<<g2, 256, GSM_TOTAL>>>(p_av, w_o, b_o, out,
                                               nullptr, nullptr, MSEQ, Hv, Hv);
}

// round 6
// speedup vs baseline: 2.5427x; 1.1571x over previous
#include <cuda_runtime.h>
#include <cuda_bf16.h>
#include <math.h>
#include <stdint.h>

// Problem constants
#define Bv   2
#define Sv   2048
#define Hv   1024
#define NHv  16
#define HDv  64
#define H3   (3 * Hv)
#define MSEQ (Bv * Sv)          // 4096 rows

// Scratch (device globals: allocation-guard safe)
__device__ __nv_bfloat16 g_xh [(size_t)MSEQ * Hv];
__device__ __nv_bfloat16 g_xl [(size_t)MSEQ * Hv];
__device__ __nv_bfloat16 g_wqh[(size_t)H3 * Hv];
__device__ __nv_bfloat16 g_wql[(size_t)H3 * Hv];
__device__ __nv_bfloat16 g_woh[(size_t)Hv * Hv];
__device__ __nv_bfloat16 g_wol[(size_t)Hv * Hv];
__device__ __nv_bfloat16 g_qkvh[(size_t)MSEQ * H3];
__device__ __nv_bfloat16 g_qkvl[(size_t)MSEQ * H3];
__device__ __nv_bfloat16 g_avh[(size_t)MSEQ * Hv];
__device__ __nv_bfloat16 g_avl[(size_t)MSEQ * Hv];

// ============================================================================
// Helpers
// ============================================================================
__device__ __forceinline__ uint32_t smem_to_u32(const void* smem_ptr) {
    uint32_t addr;
    asm("{ .reg .u64 tmp; cvta.to.shared.u64 tmp, %1; cvt.u32.u64 %0, tmp; }"
        : "=r"(addr) : "l"(smem_ptr));
    return addr;
}

__device__ __forceinline__ void ldsm_x4(uint32_t addr, uint32_t r[4]) {
    asm volatile("ldmatrix.sync.aligned.m8n8.x4.shared.b16 {%0,%1,%2,%3}, [%4];"
        : "=r"(r[0]), "=r"(r[1]), "=r"(r[2]), "=r"(r[3]) : "r"(addr));
}

__device__ __forceinline__ void ldsm_x4_t(uint32_t addr, uint32_t r[4]) {
    asm volatile("ldmatrix.sync.aligned.m8n8.x4.trans.shared.b16 {%0,%1,%2,%3}, [%4];"
        : "=r"(r[0]), "=r"(r[1]), "=r"(r[2]), "=r"(r[3]) : "r"(addr));
}

__device__ __forceinline__ void mma_bf16(float d[4], const uint32_t a[4],
                                         uint32_t b0, uint32_t b1) {
    asm volatile(
        "mma.sync.aligned.m16n8k16.row.col.f32.bf16.bf16.f32 "
        "{%0,%1,%2,%3}, {%4,%5,%6,%7}, {%8,%9}, {%0,%1,%2,%3};"
        : "+f"(d[0]), "+f"(d[1]), "+f"(d[2]), "+f"(d[3])
        : "r"(a[0]), "r"(a[1]), "r"(a[2]), "r"(a[3]), "r"(b0), "r"(b1));
}

__device__ __forceinline__ void split1(float x, uint16_t& h, uint16_t& l) {
    __nv_bfloat16 hb = __float2bfloat16_rn(x);
    float r = x - __bfloat162float(hb);
    __nv_bfloat16 lb = __float2bfloat16_rn(r);
    h = *(uint16_t*)&hb;
    l = *(uint16_t*)&lb;
}

__device__ __forceinline__ void split2(float x, float y, uint32_t& hi, uint32_t& lo) {
    uint16_t hx, lx, hy, ly;
    split1(x, hx, lx);
    split1(y, hy, ly);
    hi = (uint32_t)hx | ((uint32_t)hy << 16);
    lo = (uint32_t)lx | ((uint32_t)ly << 16);
}

#define CP_ASYNC16(dst_u32, src_ptr) \
    asm volatile("cp.async.cg.shared.global [%0], [%1], 16;" \
        :: "r"(dst_u32), "l"(src_ptr))
#define CP_ASYNC_COMMIT() asm volatile("cp.async.commit_group;" ::: "memory")
#define CP_ASYNC_WAIT(N)  asm volatile("cp.async.wait_group %0;" :: "n"(N) : "memory")

// ============================================================================
// Elementwise fp32 -> bf16 hi/lo split
// ============================================================================
__global__ __launch_bounds__(256)
void split_kernel(const float* __restrict__ src, __nv_bfloat16* __restrict__ h,
                  __nv_bfloat16* __restrict__ l, int n4)
{
    int i = blockIdx.x * blockDim.x + threadIdx.x;
    if (i < n4) {
        float4 v = ((const float4*)src)[i];
        uint2 hh, ll;
        split2(v.x, v.y, hh.x, ll.x);
        split2(v.z, v.w, hh.y, ll.y);
        ((uint2*)h)[i] = hh;
        ((uint2*)l)[i] = ll;
    }
}

// ============================================================================
// bf16x3 GEMM (NT) on pre-split inputs: C[m,n] = sum_k A[m,k]*W[n,k] + bias[n]
// CTA 128x128, KC=32, cp.async 2-stage, 2 CTAs/SM.
// Per k-step: load Ah/Al once, per-gn load Bh/Bl and fire 12 MMAs.
// ============================================================================
#define SRB   80                 // smem row stride bytes (40 bf16)
#define MATB  (128 * SRB)        // one 128x32 bf16 matrix: 10240 B
#define BUFB  (4 * MATB)         // Ah, Al, Wh, Wl: 40960 B
#define GSM_TOTAL (2 * BUFB)     // double buffered: 81920 B

template<int OUT_SPLIT>
__global__ __launch_bounds__(256, 2)
void gemm_bf16_pre(const __nv_bfloat16* __restrict__ Ah, const __nv_bfloat16* __restrict__ Al,
                   const __nv_bfloat16* __restrict__ Wh, const __nv_bfloat16* __restrict__ Wl,
                   const float* __restrict__ bias, float* __restrict__ C,
                   __nv_bfloat16* __restrict__ Ch, __nv_bfloat16* __restrict__ Cl,
                   int M, int N, int K)
{
    extern __shared__ char smem[];
    const uint32_t smb = smem_to_u32(smem);
    const int tid = threadIdx.x;
    const int lid = tid & 31;
    const int wid = tid >> 5;
    const int wm  = wid & 3;
    const int wn  = wid >> 2;
    const int m0  = blockIdx.y * 128;
    const int n0  = blockIdx.x * 128;

    const uint32_t aoff = (uint32_t)((wm * 32 + (lid & 7) + ((lid >> 3) & 1) * 8) * SRB
                                     + (lid >> 4) * 16);
    const uint32_t boff = (uint32_t)((wn * 64 + (lid & 7) + (lid >> 4) * 8) * SRB
                                     + ((lid >> 3) & 1) * 16);

    float acc[2][8][4];
#pragma unroll
    for (int i = 0; i < 2; i++)
#pragma unroll
        for (int j = 0; j < 8; j++)
#pragma unroll
            for (int e = 0; e < 4; e++) acc[i][j][e] = 0.f;

    auto LOAD = [&](int buf, int k0) {
        const uint32_t base = smb + buf * BUFB;
#pragma unroll
        for (int i = 0; i < 8; i++) {
            int idx = tid + i * 256;
            int mat = idx >> 9;          // 0:Ah 1:Al 2:Wh 3:Wl
            int rem = idx & 511;
            int r = rem >> 2;            // 0..127
            int c = rem & 3;             // 16B chunk (8 bf16)
            const __nv_bfloat16* src;
            if      (mat == 0) src = Ah + (size_t)(m0 + r) * K + k0 + c * 8;
            else if (mat == 1) src = Al + (size_t)(m0 + r) * K + k0 + c * 8;
            else if (mat == 2) src = Wh + (size_t)(n0 + r) * K + k0 + c * 8;
            else               src = Wl + (size_t)(n0 + r) * K + k0 + c * 8;
            CP_ASYNC16(base + (uint32_t)(mat * MATB + r * SRB + c * 16), src);
        }
        CP_ASYNC_COMMIT();
    };

    auto MMA = [&](int buf) {
        const uint32_t base = smb + buf * BUFB;
#pragma unroll
        for (int kt = 0; kt < 2; kt++) {
            uint32_t ah0[4], ah1[4], al0[4], al1[4];
            ldsm_x4(base + aoff + kt * 32, ah0);
            ldsm_x4(base + aoff + 16 * SRB + kt * 32, ah1);
            ldsm_x4(base + MATB + aoff + kt * 32, al0);
            ldsm_x4(base + MATB + aoff + 16 * SRB + kt * 32, al1);
#pragma unroll
            for (int gn = 0; gn < 4; gn++) {
                uint32_t bh[4], bl[4];
                ldsm_x4(base + 2 * MATB + boff + gn * (16 * SRB) + kt * 32, bh);
                ldsm_x4(base + 3 * MATB + boff + gn * (16 * SRB) + kt * 32, bl);
                // Ah * Wh
                mma_bf16(acc[0][2 * gn],     ah0, bh[0], bh[1]);
                mma_bf16(acc[0][2 * gn + 1], ah0, bh[2], bh[3]);
                mma_bf16(acc[1][2 * gn],     ah1, bh[0], bh[1]);
                mma_bf16(acc[1][2 * gn + 1], ah1, bh[2], bh[3]);
                // Al * Wh
                mma_bf16(acc[0][2 * gn],     al0, bh[0], bh[1]);
                mma_bf16(acc[0][2 * gn + 1], al0, bh[2], bh[3]);
                mma_bf16(acc[1][2 * gn],     al1, bh[0], bh[1]);
                mma_bf16(acc[1][2 * gn + 1], al1, bh[2], bh[3]);
                // Ah * Wl
                mma_bf16(acc[0][2 * gn],     ah0, bl[0], bl[1]);
                mma_bf16(acc[0][2 * gn + 1], ah0, bl[2], bl[3]);
                mma_bf16(acc[1][2 * gn],     ah1, bl[0], bl[1]);
                mma_bf16(acc[1][2 * gn + 1], ah1, bl[2], bl[3]);
            }
        }
    };

    const int NCHUNK = K / 32;
    LOAD(0, 0);
    LOAD(1, 32);

    for (int i = 0; i < NCHUNK; i++) {
        if (i + 1 < NCHUNK) { CP_ASYNC_WAIT(1); } else { CP_ASYNC_WAIT(0); }
        __syncthreads();
        MMA(i & 1);
        __syncthreads();
        if (i + 2 < NCHUNK) LOAD(i & 1, (i + 2) * 32);
    }

    // ---- Epilogue ----
#pragma unroll
    for (int mt = 0; mt < 2; mt++) {
        const int row = m0 + wm * 32 + mt * 16 + (lid >> 2);
#pragma unroll
        for (int nt = 0; nt < 8; nt++) {
            const int col = n0 + wn * 64 + nt * 8 + (lid & 3) * 2;
            const float b0 = bias[col], b1 = bias[col + 1];
            float v00 = acc[mt][nt][0] + b0, v01 = acc[mt][nt][1] + b1;
            float v10 = acc[mt][nt][2] + b0, v11 = acc[mt][nt][3] + b1;
            if (OUT_SPLIT) {
                uint32_t h0, l0, h1, l1;
                split2(v00, v01, h0, l0);
                split2(v10, v11, h1, l1);
                *(uint32_t*)(Ch + (size_t)row * N + col)       = h0;
                *(uint32_t*)(Cl + (size_t)row * N + col)       = l0;
                *(uint32_t*)(Ch + (size_t)(row + 8) * N + col) = h1;
                *(uint32_t*)(Cl + (size_t)(row + 8) * N + col) = l1;
            } else {
                *(float2*)(C + (size_t)row * N + col)       = make_float2(v00, v01);
                *(float2*)(C + (size_t)(row + 8) * N + col) = make_float2(v10, v11);
            }
        }
    }
}

// ============================================================================
// Tensor-core flash attention (bf16x3); epilogue writes split bf16 av.
// ============================================================================
#define SRA   144                 // bf16 tile row stride bytes (72 bf16)
#define QTB   (128 * SRA)
#define KVTB  (64 * SRA)
#define AS_QH 0
#define AS_QL QTB
#define AS_KV (2 * QTB)
#define AS_MS (AS_KV + 2 * 4 * KVTB)
#define ATT_SMEM (AS_MS + Sv * 4)

__global__ __launch_bounds__(256)
void attn_mma(const __nv_bfloat16* __restrict__ qh,
              const __nv_bfloat16* __restrict__ ql,
              const float* __restrict__ mask,
              __nv_bfloat16* __restrict__ avh, __nv_bfloat16* __restrict__ avl)
{
    extern __shared__ char smem[];
    const uint32_t smb = smem_to_u32(smem);
    const int tid = threadIdx.x;
    const int lid = tid & 31;
    const int wq  = tid >> 5;
    const int q0  = blockIdx.x * 128;
    const int h   = blockIdx.y;
    const int b   = blockIdx.z;
    const size_t rowbase = (size_t)b * Sv;
    const int hd0 = h * HDv;

#pragma unroll
    for (int i = 0; i < 2; i++) {
        int idx = tid + i * 256;
        CP_ASYNC16(smb + AS_MS + idx * 16, mask + idx * 4);
    }
#pragma unroll
    for (int i = 0; i < 8; i++) {
        int idx = tid + i * 256;
        int mat = idx >> 10, rem = idx & 1023;
        int r = rem >> 3, c = rem & 7;
        const __nv_bfloat16* src = (mat ? ql : qh)
            + (rowbase + q0 + r) * H3 + hd0 + c * 8;
        CP_ASYNC16(smb + (mat ? AS_QL : AS_QH) + r * SRA + c * 16, src);
    }
#pragma unroll
    for (int i = 0; i < 8; i++) {
        int idx = tid + i * 256;
        int mat = idx >> 9, rem = idx & 511;
        int r = rem >> 3, c = rem & 7;
        const __nv_bfloat16* base = (mat & 1) ? ql : qh;
        int off = (mat >> 1) ? 2 * Hv : Hv;
        CP_ASYNC16(smb + AS_KV + mat * KVTB + r * SRA + c * 16,
                   base + (rowbase + r) * H3 + off + hd0 + c * 8);
    }
    CP_ASYNC_COMMIT();

    const uint32_t aoffQ = (uint32_t)((wq * 16 + (lid & 7) + ((lid >> 3) & 1) * 8) * SRA
                                      + (lid >> 4) * 16);
    const uint32_t boffK = (uint32_t)(((lid & 7) + (lid >> 4) * 8) * SRA
                                      + ((lid >> 3) & 1) * 16);
    const uint32_t voffV = (uint32_t)(((lid & 7) + ((lid >> 3) & 1) * 8) * SRA
                                      + (lid >> 4) * 16);

    float o[8][4];
#pragma unroll
    for (int j = 0; j < 8; j++)
#pragma unroll
        for (int e = 0; e < 4; e++) o[j][e] = 0.f;
    float m0 = -INFINITY, m1 = -INFINITY, l0 = 0.f, l1 = 0.f;

    const int NT = Sv / 64;
    for (int t = 0; t < NT; t++) {
        __syncthreads();
        if (t + 1 < NT) {
            const int kb = (t + 1) * 64;
            const uint32_t kvb = smb + AS_KV + ((t + 1) & 1) * (4 * KVTB);
#pragma unroll
            for (int i = 0; i < 8; i++) {
                int idx = tid + i * 256;
                int mat = idx >> 9, rem = idx & 511;
                int r = rem >> 3, c = rem & 7;
                const __nv_bfloat16* base = (mat & 1) ? ql : qh;
                int off = (mat >> 1) ? 2 * Hv : Hv;
                CP_ASYNC16(kvb + mat * KVTB + r * SRA + c * 16,
                           base + (rowbase + kb + r) * H3 + off + hd0 + c * 8);
            }
            CP_ASYNC_COMMIT();
            CP_ASYNC_WAIT(1);
        } else {
            CP_ASYNC_WAIT(0);
        }
        __syncthreads();

        const uint32_t kvb = smb + AS_KV + (t & 1) * (4 * KVTB);
        const uint32_t KH = kvb, KL = kvb + KVTB, VH = kvb + 2 * KVTB, VL = kvb + 3 * KVTB;

        // ---- S = Q K^T (bf16x3) ----
        float s[8][4];
#pragma unroll
        for (int j = 0; j < 8; j++)
#pragma unroll
            for (int e = 0; e < 4; e++) s[j][e] = 0.f;

#pragma unroll
        for (int kt = 0; kt < 4; kt++) {
            uint32_t aQh[4], aQl[4];
            ldsm_x4(smb + AS_QH + aoffQ + kt * 32, aQh);
            ldsm_x4(smb + AS_QL + aoffQ + kt * 32, aQl);
#pragma unroll
            for (int gn = 0; gn < 4; gn++) {
                uint32_t bh[4], bl[4];
                ldsm_x4(KH + boffK + gn * (16 * SRA) + kt * 32, bh);
                ldsm_x4(KL + boffK + gn * (16 * SRA) + kt * 32, bl);
                mma_bf16(s[2 * gn],     aQh, bh[0], bh[1]);
                mma_bf16(s[2 * gn + 1], aQh, bh[2], bh[3]);
                mma_bf16(s[2 * gn],     aQl, bh[0], bh[1]);
                mma_bf16(s[2 * gn + 1], aQl, bh[2], bh[3]);
                mma_bf16(s[2 * gn],     aQh, bl[0], bl[1]);
                mma_bf16(s[2 * gn + 1], aQh, bl[2], bl[3]);
            }
        }

        // ---- online softmax ----
        const uint32_t msb = smb + AS_MS + (uint32_t)((t * 64 + 2 * (lid & 3)) * 4);
        float tm0 = -INFINITY, tm1 = -INFINITY;
#pragma unroll
        for (int j = 0; j < 8; j++) {
            float mkx, mky;
            asm("ld.shared.v2.f32 {%0,%1}, [%2];" : "=f"(mkx), "=f"(mky) : "r"(msb + j * 32));
            s[j][0] = (s[j][0] + mkx) * 0.125f;
            s[j][1] = (s[j][1] + mky) * 0.125f;
            s[j][2] = (s[j][2] + mkx) * 0.125f;
            s[j][3] = (s[j][3] + mky) * 0.125f;
            tm0 = fmaxf(tm0, fmaxf(s[j][0], s[j][1]));
            tm1 = fmaxf(tm1, fmaxf(s[j][2], s[j][3]));
        }
        tm0 = fmaxf(tm0, __shfl_xor_sync(0xffffffffu, tm0, 1));
        tm0 = fmaxf(tm0, __shfl_xor_sync(0xffffffffu, tm0, 2));
        tm1 = fmaxf(tm1, __shfl_xor_sync(0xffffffffu, tm1, 1));
        tm1 = fmaxf(tm1, __shfl_xor_sync(0xffffffffu, tm1, 2));

        const float mn0 = fmaxf(m0, tm0), mn1 = fmaxf(m1, tm1);
        const float al0 = __expf(m0 - mn0), al1 = __expf(m1 - mn1);
        m0 = mn0; m1 = mn1;

        float rs0 = 0.f, rs1 = 0.f;
#pragma unroll
        for (int j = 0; j < 8; j++) {
            s[j][0] = __expf(s[j][0] - mn0);
            s[j][1] = __expf(s[j][1] - mn0);
            s[j][2] = __expf(s[j][2] - mn1);
            s[j][3] = __expf(s[j][3] - mn1);
            rs0 += s[j][0] + s[j][1];
            rs1 += s[j][2] + s[j][3];
        }
        rs0 += __shfl_xor_sync(0xffffffffu, rs0, 1);
        rs0 += __shfl_xor_sync(0xffffffffu, rs0, 2);
        rs1 += __shfl_xor_sync(0xffffffffu, rs1, 1);
        rs1 += __shfl_xor_sync(0xffffffffu, rs1, 2);
        l0 = l0 * al0 + rs0;
        l1 = l1 * al1 + rs1;

#pragma unroll
        for (int j = 0; j < 8; j++) {
            o[j][0] *= al0; o[j][1] *= al0;
            o[j][2] *= al1; o[j][3] *= al1;
        }

        // ---- O += P V (bf16x3) ----
#pragma unroll
        for (int kt = 0; kt < 4; kt++) {
            uint32_t ah[4], al_[4];
            split2(s[2 * kt][0],     s[2 * kt][1],     ah[0], al_[0]);
            split2(s[2 * kt][2],     s[2 * kt][3],     ah[1], al_[1]);
            split2(s[2 * kt + 1][0], s[2 * kt + 1][1], ah[2], al_[2]);
            split2(s[2 * kt + 1][2], s[2 * kt + 1][3], ah[3], al_[3]);
#pragma unroll
            for (int jp = 0; jp < 4; jp++) {
                uint32_t bh[4], bl[4];
                ldsm_x4_t(VH + voffV + kt * (16 * SRA) + jp * 32, bh);
                ldsm_x4_t(VL + voffV + kt * (16 * SRA) + jp * 32, bl);
                mma_bf16(o[2 * jp],     ah,  bh[0], bh[1]);
                mma_bf16(o[2 * jp + 1], ah,  bh[2], bh[3]);
                mma_bf16(o[2 * jp],     al_, bh[0], bh[1]);
                mma_bf16(o[2 * jp + 1], al_, bh[2], bh[3]);
                mma_bf16(o[2 * jp],     ah,  bl[0], bl[1]);
                mma_bf16(o[2 * jp + 1], ah,  bl[2], bl[3]);
            }
        }
    }

    // ---- Epilogue: normalize, split, store avh/avl[b*s][h*64+d] ----
    const float inv0 = 1.f / l0, inv1 = 1.f / l1;
    const int rg = q0 + wq * 16 + (lid >> 2);
    const size_t obase = (rowbase + rg) * Hv + hd0 + 2 * (lid & 3);
#pragma unroll
    for (int j = 0; j < 8; j++) {
        uint32_t h0, l0u, h1, l1u;
        split2(o[j][0] * inv0, o[j][1] * inv0, h0, l0u);
        split2(o[j][2] * inv1, o[j][3] * inv1, h1, l1u);
        *(uint32_t*)(avh + obase + j * 8)          = h0;
        *(uint32_t*)(avl + obase + j * 8)          = l0u;
        *(uint32_t*)(avh + obase + 8 * Hv + j * 8) = h1;
        *(uint32_t*)(avl + obase + 8 * Hv + j * 8) = l1u;
    }
}

// ============================================================================
// Launch
// ============================================================================
extern "C" void kernel_launch(void* const* d_in, const int* in_sizes, int n_in,
                              void* d_out, int out_size)
{
    const float* x     = (const float*)d_in[0];
    const float* mask  = (const float*)d_in[1];
    const float* w_qkv = (const float*)d_in[2];
    const float* b_qkv = (const float*)d_in[3];
    const float* w_o   = (const float*)d_in[4];
    const float* b_o   = (const float*)d_in[5];
    float* out = (float*)d_out;

    __nv_bfloat16 *p_xh, *p_xl, *p_wqh, *p_wql, *p_woh, *p_wol;
    __nv_bfloat16 *p_qkvh, *p_qkvl, *p_avh, *p_avl;
    cudaGetSymbolAddress((void**)&p_xh, g_xh);
    cudaGetSymbolAddress((void**)&p_xl, g_xl);
    cudaGetSymbolAddress((void**)&p_wqh, g_wqh);
    cudaGetSymbolAddress((void**)&p_wql, g_wql);
    cudaGetSymbolAddress((void**)&p_woh, g_woh);
    cudaGetSymbolAddress((void**)&p_wol, g_wol);
    cudaGetSymbolAddress((void**)&p_qkvh, g_qkvh);
    cudaGetSymbolAddress((void**)&p_qkvl, g_qkvl);
    cudaGetSymbolAddress((void**)&p_avh, g_avh);
    cudaGetSymbolAddress((void**)&p_avl, g_avl);

    cudaFuncSetAttribute(gemm_bf16_pre<1>,
                         cudaFuncAttributeMaxDynamicSharedMemorySize, GSM_TOTAL);
    cudaFuncSetAttribute(gemm_bf16_pre<0>,
                         cudaFuncAttributeMaxDynamicSharedMemorySize, GSM_TOTAL);
    cudaFuncSetAttribute(attn_mma,
                         cudaFuncAttributeMaxDynamicSharedMemorySize, ATT_SMEM);

    // 0) Pre-split inputs to bf16 hi/lo
    split_kernel<<<(MSEQ * Hv / 4 + 255) / 256, 256>>>(x, p_xh, p_xl, MSEQ * Hv / 4);
    split_kernel<<<(H3 * Hv / 4 + 255) / 256, 256>>>(w_qkv, p_wqh, p_wql, H3 * Hv / 4);
    split_kernel<<<(Hv * Hv / 4 + 255) / 256, 256>>>(w_o, p_woh, p_wol, Hv * Hv / 4);

    // 1) QKV projection -> split bf16 hi/lo
    dim3 g1(H3 / 128, MSEQ / 128);
    gemm_bf16_pre<1><<<g1, 256, GSM_TOTAL>>>(p_xh, p_xl, p_wqh, p_wql, b_qkv,
                                             nullptr, p_qkvh, p_qkvl, MSEQ, H3, Hv);

    // 2) Tensor-core flash attention -> split av
    attn_mma<<<dim3(Sv / 128, NHv, Bv), 256, ATT_SMEM>>>(p_qkvh, p_qkvl, mask,
                                                         p_avh, p_avl);

    // 3) Output projection -> out fp32
    dim3 g2(Hv / 128, MSEQ / 128);
    gemm_bf16_pre<0><<<g2, 256, GSM_TOTAL>>>(p_avh, p_avl, p_woh, p_wol, b_o,
                                             out, nullptr, nullptr, MSEQ, Hv, Hv);
}

// round 7
// speedup vs baseline: 6.5092x; 2.5599x over previous
#include <cuda_runtime.h>
#include <cuda_fp16.h>
#include <math.h>
#include <stdint.h>

// Problem constants
#define Bv   2
#define Sv   2048
#define Hv   1024
#define NHv  16
#define HDv  64
#define H3   (3 * Hv)
#define MSEQ (Bv * Sv)          // 4096 rows

// Scratch (device globals: allocation-guard safe)
__device__ __half g_x [(size_t)MSEQ * Hv];
__device__ __half g_wq[(size_t)H3 * Hv];
__device__ __half g_wo[(size_t)Hv * Hv];
__device__ __half g_qkv[(size_t)MSEQ * H3];
__device__ __half g_av[(size_t)MSEQ * Hv];

// ============================================================================
// Helpers
// ============================================================================
__device__ __forceinline__ uint32_t smem_to_u32(const void* smem_ptr) {
    uint32_t addr;
    asm("{ .reg .u64 tmp; cvta.to.shared.u64 tmp, %1; cvt.u32.u64 %0, tmp; }"
        : "=r"(addr) : "l"(smem_ptr));
    return addr;
}

__device__ __forceinline__ void ldsm_x4(uint32_t addr, uint32_t r[4]) {
    asm volatile("ldmatrix.sync.aligned.m8n8.x4.shared.b16 {%0,%1,%2,%3}, [%4];"
        : "=r"(r[0]), "=r"(r[1]), "=r"(r[2]), "=r"(r[3]) : "r"(addr));
}

__device__ __forceinline__ void ldsm_x4_t(uint32_t addr, uint32_t r[4]) {
    asm volatile("ldmatrix.sync.aligned.m8n8.x4.trans.shared.b16 {%0,%1,%2,%3}, [%4];"
        : "=r"(r[0]), "=r"(r[1]), "=r"(r[2]), "=r"(r[3]) : "r"(addr));
}

__device__ __forceinline__ void mma_f16(float d[4], const uint32_t a[4],
                                        uint32_t b0, uint32_t b1) {
    asm volatile(
        "mma.sync.aligned.m16n8k16.row.col.f32.f16.f16.f32 "
        "{%0,%1,%2,%3}, {%4,%5,%6,%7}, {%8,%9}, {%0,%1,%2,%3};"
        : "+f"(d[0]), "+f"(d[1]), "+f"(d[2]), "+f"(d[3])
        : "r"(a[0]), "r"(a[1]), "r"(a[2]), "r"(a[3]), "r"(b0), "r"(b1));
}

__device__ __forceinline__ uint32_t pack_h2(float x, float y) {
    __half2 h = __float22half2_rn(make_float2(x, y));
    return *(uint32_t*)&h;
}

#define CP_ASYNC16(dst_u32, src_ptr) \
    asm volatile("cp.async.cg.shared.global [%0], [%1], 16;" \
        :: "r"(dst_u32), "l"(src_ptr))
#define CP_ASYNC_COMMIT() asm volatile("cp.async.commit_group;" ::: "memory")
#define CP_ASYNC_WAIT(N)  asm volatile("cp.async.wait_group %0;" :: "n"(N) : "memory")

// ============================================================================
// Elementwise fp32 -> fp16
// ============================================================================
__global__ __launch_bounds__(256)
void cvt_kernel(const float* __restrict__ src, __half* __restrict__ dst, int n4)
{
    int i = blockIdx.x * blockDim.x + threadIdx.x;
    if (i < n4) {
        float4 v = ((const float4*)src)[i];
        uint2 o;
        o.x = pack_h2(v.x, v.y);
        o.y = pack_h2(v.z, v.w);
        ((uint2*)dst)[i] = o;
    }
}

// ============================================================================
// fp16 GEMM (NT): C[m,n] = sum_k A[m,k]*W[n,k] + bias[n]
// CTA 128x128, KC=64, 3-stage cp.async pipeline (one sync/iter), 2 CTAs/SM.
// 8 warps (4m x 2n), warp tile 32x64.
// ============================================================================
#define SRB   144                // smem row stride bytes (64 fp16 = 128B + 16 pad)
#define MATB  (128 * SRB)        // one 128x64 fp16 matrix: 18432 B
#define STGB  (2 * MATB)         // A, W: 36864 B per stage
#define GSM_TOTAL (3 * STGB)     // 3 stages: 110592 B

template<int OUT_HALF>
__global__ __launch_bounds__(256, 2)
void gemm_f16(const __half* __restrict__ A, const __half* __restrict__ W,
              const float* __restrict__ bias, float* __restrict__ C,
              __half* __restrict__ Ch, int M, int N, int K)
{
    extern __shared__ char smem[];
    const uint32_t smb = smem_to_u32(smem);
    const int tid = threadIdx.x;
    const int lid = tid & 31;
    const int wid = tid >> 5;
    const int wm  = wid & 3;          // m-warp (x32 rows)
    const int wn  = wid >> 2;         // n-warp (x64 cols)
    const int m0  = blockIdx.y * 128;
    const int n0  = blockIdx.x * 128;

    const uint32_t aoff = (uint32_t)((wm * 32 + (lid & 7) + ((lid >> 3) & 1) * 8) * SRB
                                     + (lid >> 4) * 16);
    const uint32_t boff = (uint32_t)((wn * 64 + (lid & 7) + (lid >> 4) * 8) * SRB
                                     + ((lid >> 3) & 1) * 16);

    float acc[2][8][4];
#pragma unroll
    for (int i = 0; i < 2; i++)
#pragma unroll
        for (int j = 0; j < 8; j++)
#pragma unroll
            for (int e = 0; e < 4; e++) acc[i][j][e] = 0.f;

    auto LOAD = [&](int buf, int chunk) {
        const uint32_t base = smb + buf * STGB;
        const int k0 = chunk * 64;
#pragma unroll
        for (int i = 0; i < 8; i++) {
            int idx = tid + i * 256;          // 0..2047
            int mat = idx >> 10;              // 0:A 1:W
            int rem = idx & 1023;
            int r = rem >> 3;                 // 0..127
            int c = rem & 7;                  // 16B chunk (8 fp16)
            const __half* src = mat
                ? W + (size_t)(n0 + r) * K + k0 + c * 8
                : A + (size_t)(m0 + r) * K + k0 + c * 8;
            CP_ASYNC16(base + (uint32_t)(mat * MATB + r * SRB + c * 16), src);
        }
        CP_ASYNC_COMMIT();
    };

    auto MMA = [&](int buf) {
        const uint32_t base = smb + buf * STGB;
#pragma unroll
        for (int kt = 0; kt < 4; kt++) {
            uint32_t a0[4], a1[4];
            ldsm_x4(base + aoff + kt * 32, a0);
            ldsm_x4(base + aoff + 16 * SRB + kt * 32, a1);
#pragma unroll
            for (int gn = 0; gn < 4; gn++) {
                uint32_t bb[4];
                ldsm_x4(base + MATB + boff + gn * (16 * SRB) + kt * 32, bb);
                mma_f16(acc[0][2 * gn],     a0, bb[0], bb[1]);
                mma_f16(acc[0][2 * gn + 1], a0, bb[2], bb[3]);
                mma_f16(acc[1][2 * gn],     a1, bb[0], bb[1]);
                mma_f16(acc[1][2 * gn + 1], a1, bb[2], bb[3]);
            }
        }
    };

    const int NCHUNK = K / 64;
    LOAD(0, 0);
    LOAD(1, 1);

    for (int i = 0; i < NCHUNK; i++) {
        if (i + 1 < NCHUNK) { CP_ASYNC_WAIT(1); } else { CP_ASYNC_WAIT(0); }
        __syncthreads();
        if (i + 2 < NCHUNK) LOAD((i + 2) % 3, i + 2);
        MMA(i % 3);
    }

    // ---- Epilogue ----
#pragma unroll
    for (int mt = 0; mt < 2; mt++) {
        const int row = m0 + wm * 32 + mt * 16 + (lid >> 2);
#pragma unroll
        for (int nt = 0; nt < 8; nt++) {
            const int col = n0 + wn * 64 + nt * 8 + (lid & 3) * 2;
            const float b0 = bias[col], b1 = bias[col + 1];
            float v00 = acc[mt][nt][0] + b0, v01 = acc[mt][nt][1] + b1;
            float v10 = acc[mt][nt][2] + b0, v11 = acc[mt][nt][3] + b1;
            if (OUT_HALF) {
                *(uint32_t*)(Ch + (size_t)row * N + col)       = pack_h2(v00, v01);
                *(uint32_t*)(Ch + (size_t)(row + 8) * N + col) = pack_h2(v10, v11);
            } else {
                *(float2*)(C + (size_t)row * N + col)       = make_float2(v00, v01);
                *(float2*)(C + (size_t)(row + 8) * N + col) = make_float2(v10, v11);
            }
        }
    }
}

// ============================================================================
// fp16 tensor-core flash attention.
// CTA: 128 q-rows x one (b,h). 8 warps x 16 q-rows. K-tile = 64 keys.
// SMEM ~62KB -> 2 CTAs/SM. Double-buffered K/V via cp.async.
// ============================================================================
#define SRA   144                 // fp16 tile row stride bytes (64 fp16 + pad)
#define QTB   (128 * SRA)         // 18432
#define KVTB  (64 * SRA)          // 9216
#define AS_Q  0
#define AS_KV QTB                          // 2 buf x (K,V): 4 x 9216
#define AS_MS (AS_KV + 2 * 2 * KVTB)       // 55296
#define ATT_SMEM (AS_MS + Sv * 4)          // +8192 = 63488

__global__ __launch_bounds__(256, 2)
void attn_mma(const __half* __restrict__ qkv, const float* __restrict__ mask,
              __half* __restrict__ av)
{
    extern __shared__ char smem[];
    const uint32_t smb = smem_to_u32(smem);
    const int tid = threadIdx.x;
    const int lid = tid & 31;
    const int wq  = tid >> 5;
    const int q0  = blockIdx.x * 128;
    const int h   = blockIdx.y;
    const int b   = blockIdx.z;
    const size_t rowbase = (size_t)b * Sv;
    const int hd0 = h * HDv;

    // ---- preload: mask + Q + KV tile 0, one cp.async group ----
#pragma unroll
    for (int i = 0; i < 2; i++) {
        int idx = tid + i * 256;
        CP_ASYNC16(smb + AS_MS + idx * 16, mask + idx * 4);
    }
#pragma unroll
    for (int i = 0; i < 4; i++) {
        int idx = tid + i * 256;                 // 0..1023
        int r = idx >> 3, c = idx & 7;
        CP_ASYNC16(smb + AS_Q + r * SRA + c * 16,
                   qkv + (rowbase + q0 + r) * H3 + hd0 + c * 8);
    }
#pragma unroll
    for (int i = 0; i < 4; i++) {
        int idx = tid + i * 256;                 // 0..1023
        int mat = idx >> 9;                      // 0:K 1:V
        int rem = idx & 511;
        int r = rem >> 3, c = rem & 7;
        int off = mat ? 2 * Hv : Hv;
        CP_ASYNC16(smb + AS_KV + mat * KVTB + r * SRA + c * 16,
                   qkv + (rowbase + r) * H3 + off + hd0 + c * 8);
    }
    CP_ASYNC_COMMIT();

    const uint32_t aoffQ = (uint32_t)((wq * 16 + (lid & 7) + ((lid >> 3) & 1) * 8) * SRA
                                      + (lid >> 4) * 16);
    const uint32_t boffK = (uint32_t)(((lid & 7) + (lid >> 4) * 8) * SRA
                                      + ((lid >> 3) & 1) * 16);
    const uint32_t voffV = (uint32_t)(((lid & 7) + ((lid >> 3) & 1) * 8) * SRA
                                      + (lid >> 4) * 16);

    float o[8][4];
#pragma unroll
    for (int j = 0; j < 8; j++)
#pragma unroll
        for (int e = 0; e < 4; e++) o[j][e] = 0.f;
    float m0 = -INFINITY, m1 = -INFINITY, l0 = 0.f, l1 = 0.f;

    const int NT = Sv / 64;
    for (int t = 0; t < NT; t++) {
        __syncthreads();
        if (t + 1 < NT) {
            const int kb = (t + 1) * 64;
            const uint32_t kvb = smb + AS_KV + ((t + 1) & 1) * (2 * KVTB);
#pragma unroll
            for (int i = 0; i < 4; i++) {
                int idx = tid + i * 256;
                int mat = idx >> 9;
                int rem = idx & 511;
                int r = rem >> 3, c = rem & 7;
                int off = mat ? 2 * Hv : Hv;
                CP_ASYNC16(kvb + mat * KVTB + r * SRA + c * 16,
                           qkv + (rowbase + kb + r) * H3 + off + hd0 + c * 8);
            }
            CP_ASYNC_COMMIT();
            CP_ASYNC_WAIT(1);
        } else {
            CP_ASYNC_WAIT(0);
        }
        __syncthreads();

        const uint32_t kvb = smb + AS_KV + (t & 1) * (2 * KVTB);
        const uint32_t KB = kvb, VB = kvb + KVTB;

        // ---- S = Q K^T ----
        float s[8][4];
#pragma unroll
        for (int j = 0; j < 8; j++)
#pragma unroll
            for (int e = 0; e < 4; e++) s[j][e] = 0.f;

#pragma unroll
        for (int kt = 0; kt < 4; kt++) {
            uint32_t aQ[4];
            ldsm_x4(smb + AS_Q + aoffQ + kt * 32, aQ);
#pragma unroll
            for (int gn = 0; gn < 4; gn++) {
                uint32_t bb[4];
                ldsm_x4(KB + boffK + gn * (16 * SRA) + kt * 32, bb);
                mma_f16(s[2 * gn],     aQ, bb[0], bb[1]);
                mma_f16(s[2 * gn + 1], aQ, bb[2], bb[3]);
            }
        }

        // ---- online softmax ----
        const uint32_t msb = smb + AS_MS + (uint32_t)((t * 64 + 2 * (lid & 3)) * 4);
        float tm0 = -INFINITY, tm1 = -INFINITY;
#pragma unroll
        for (int j = 0; j < 8; j++) {
            float mkx, mky;
            asm("ld.shared.v2.f32 {%0,%1}, [%2];" : "=f"(mkx), "=f"(mky) : "r"(msb + j * 32));
            s[j][0] = (s[j][0] + mkx) * 0.125f;
            s[j][1] = (s[j][1] + mky) * 0.125f;
            s[j][2] = (s[j][2] + mkx) * 0.125f;
            s[j][3] = (s[j][3] + mky) * 0.125f;
            tm0 = fmaxf(tm0, fmaxf(s[j][0], s[j][1]));
            tm1 = fmaxf(tm1, fmaxf(s[j][2], s[j][3]));
        }
        tm0 = fmaxf(tm0, __shfl_xor_sync(0xffffffffu, tm0, 1));
        tm0 = fmaxf(tm0, __shfl_xor_sync(0xffffffffu, tm0, 2));
        tm1 = fmaxf(tm1, __shfl_xor_sync(0xffffffffu, tm1, 1));
        tm1 = fmaxf(tm1, __shfl_xor_sync(0xffffffffu, tm1, 2));

        const float mn0 = fmaxf(m0, tm0), mn1 = fmaxf(m1, tm1);
        const float al0 = __expf(m0 - mn0), al1 = __expf(m1 - mn1);
        m0 = mn0; m1 = mn1;

        float rs0 = 0.f, rs1 = 0.f;
#pragma unroll
        for (int j = 0; j < 8; j++) {
            s[j][0] = __expf(s[j][0] - mn0);
            s[j][1] = __expf(s[j][1] - mn0);
            s[j][2] = __expf(s[j][2] - mn1);
            s[j][3] = __expf(s[j][3] - mn1);
            rs0 += s[j][0] + s[j][1];
            rs1 += s[j][2] + s[j][3];
        }
        rs0 += __shfl_xor_sync(0xffffffffu, rs0, 1);
        rs0 += __shfl_xor_sync(0xffffffffu, rs0, 2);
        rs1 += __shfl_xor_sync(0xffffffffu, rs1, 1);
        rs1 += __shfl_xor_sync(0xffffffffu, rs1, 2);
        l0 = l0 * al0 + rs0;
        l1 = l1 * al1 + rs1;

#pragma unroll
        for (int j = 0; j < 8; j++) {
            o[j][0] *= al0; o[j][1] *= al0;
            o[j][2] *= al1; o[j][3] *= al1;
        }

        // ---- O += P V ----
#pragma unroll
        for (int kt = 0; kt < 4; kt++) {
            uint32_t ap[4];
            ap[0] = pack_h2(s[2 * kt][0],     s[2 * kt][1]);
            ap[1] = pack_h2(s[2 * kt][2],     s[2 * kt][3]);
            ap[2] = pack_h2(s[2 * kt + 1][0], s[2 * kt + 1][1]);
            ap[3] = pack_h2(s[2 * kt + 1][2], s[2 * kt + 1][3]);
#pragma unroll
            for (int jp = 0; jp < 4; jp++) {
                uint32_t bb[4];
                ldsm_x4_t(VB + voffV + kt * (16 * SRA) + jp * 32, bb);
                mma_f16(o[2 * jp],     ap, bb[0], bb[1]);
                mma_f16(o[2 * jp + 1], ap, bb[2], bb[3]);
            }
        }
    }

    // ---- Epilogue: normalize, store fp16 av[b*s][h*64+d] ----
    const float inv0 = 1.f / l0, inv1 = 1.f / l1;
    const int rg = q0 + wq * 16 + (lid >> 2);
    const size_t obase = (rowbase + rg) * Hv + hd0 + 2 * (lid & 3);
#pragma unroll
    for (int j = 0; j < 8; j++) {
        *(uint32_t*)(av + obase + j * 8)          = pack_h2(o[j][0] * inv0, o[j][1] * inv0);
        *(uint32_t*)(av + obase + 8 * Hv + j * 8) = pack_h2(o[j][2] * inv1, o[j][3] * inv1);
    }
}

// ============================================================================
// Launch
// ============================================================================
extern "C" void kernel_launch(void* const* d_in, const int* in_sizes, int n_in,
                              void* d_out, int out_size)
{
    const float* x     = (const float*)d_in[0];
    const float* mask  = (const float*)d_in[1];
    const float* w_qkv = (const float*)d_in[2];
    const float* b_qkv = (const float*)d_in[3];
    const float* w_o   = (const float*)d_in[4];
    const float* b_o   = (const float*)d_in[5];
    float* out = (float*)d_out;

    __half *p_x, *p_wq, *p_wo, *p_qkv, *p_av;
    cudaGetSymbolAddress((void**)&p_x, g_x);
    cudaGetSymbolAddress((void**)&p_wq, g_wq);
    cudaGetSymbolAddress((void**)&p_wo, g_wo);
    cudaGetSymbolAddress((void**)&p_qkv, g_qkv);
    cudaGetSymbolAddress((void**)&p_av, g_av);

    cudaFuncSetAttribute(gemm_f16<1>,
                         cudaFuncAttributeMaxDynamicSharedMemorySize, GSM_TOTAL);
    cudaFuncSetAttribute(gemm_f16<0>,
                         cudaFuncAttributeMaxDynamicSharedMemorySize, GSM_TOTAL);
    cudaFuncSetAttribute(attn_mma,
                         cudaFuncAttributeMaxDynamicSharedMemorySize, ATT_SMEM);

    // 0) Convert inputs to fp16
    cvt_kernel<<<(MSEQ * Hv / 4 + 255) / 256, 256>>>(x, p_x, MSEQ * Hv / 4);
    cvt_kernel<<<(H3 * Hv / 4 + 255) / 256, 256>>>(w_qkv, p_wq, H3 * Hv / 4);
    cvt_kernel<<<(Hv * Hv / 4 + 255) / 256, 256>>>(w_o, p_wo, Hv * Hv / 4);

    // 1) QKV projection -> fp16 qkv
    dim3 g1(H3 / 128, MSEQ / 128);
    gemm_f16<1><<<g1, 256, GSM_TOTAL>>>(p_x, p_wq, b_qkv, nullptr, p_qkv,
                                        MSEQ, H3, Hv);

    // 2) fp16 flash attention -> fp16 av
    attn_mma<<<dim3(Sv / 128, NHv, Bv), 256, ATT_SMEM>>>(p_qkv, mask, p_av);

    // 3) Output projection -> fp32 out
    dim3 g2(Hv / 128, MSEQ / 128);
    gemm_f16<0><<<g2, 256, GSM_TOTAL>>>(p_av, p_wo, b_o, out, nullptr,
                                        MSEQ, Hv, Hv);
}

// round 8
// speedup vs baseline: 6.6260x; 1.0180x over previous
#include <cuda_runtime.h>
#include <cuda_fp16.h>
#include <math.h>
#include <stdint.h>

// Problem constants
#define Bv   2
#define Sv   2048
#define Hv   1024
#define NHv  16
#define HDv  64
#define H3   (3 * Hv)
#define MSEQ (Bv * Sv)          // 4096 rows

// Scratch (device globals: allocation-guard safe)
__device__ __half g_x [(size_t)MSEQ * Hv];
__device__ __half g_wq[(size_t)H3 * Hv];
__device__ __half g_wo[(size_t)Hv * Hv];
__device__ __half g_qkv[(size_t)MSEQ * H3];
__device__ __half g_av[(size_t)MSEQ * Hv];

// ============================================================================
// Helpers
// ============================================================================
__device__ __forceinline__ uint32_t smem_to_u32(const void* smem_ptr) {
    uint32_t addr;
    asm("{ .reg .u64 tmp; cvta.to.shared.u64 tmp, %1; cvt.u32.u64 %0, tmp; }"
        : "=r"(addr) : "l"(smem_ptr));
    return addr;
}

__device__ __forceinline__ void ldsm_x4(uint32_t addr, uint32_t r[4]) {
    asm volatile("ldmatrix.sync.aligned.m8n8.x4.shared.b16 {%0,%1,%2,%3}, [%4];"
        : "=r"(r[0]), "=r"(r[1]), "=r"(r[2]), "=r"(r[3]) : "r"(addr));
}

__device__ __forceinline__ void ldsm_x4_t(uint32_t addr, uint32_t r[4]) {
    asm volatile("ldmatrix.sync.aligned.m8n8.x4.trans.shared.b16 {%0,%1,%2,%3}, [%4];"
        : "=r"(r[0]), "=r"(r[1]), "=r"(r[2]), "=r"(r[3]) : "r"(addr));
}

__device__ __forceinline__ void mma_f16(float d[4], const uint32_t a[4],
                                        uint32_t b0, uint32_t b1) {
    asm volatile(
        "mma.sync.aligned.m16n8k16.row.col.f32.f16.f16.f32 "
        "{%0,%1,%2,%3}, {%4,%5,%6,%7}, {%8,%9}, {%0,%1,%2,%3};"
        : "+f"(d[0]), "+f"(d[1]), "+f"(d[2]), "+f"(d[3])
        : "r"(a[0]), "r"(a[1]), "r"(a[2]), "r"(a[3]), "r"(b0), "r"(b1));
}

__device__ __forceinline__ uint32_t pack_h2(float x, float y) {
    __half2 h = __float22half2_rn(make_float2(x, y));
    return *(uint32_t*)&h;
}

#define CP_ASYNC16(dst_u32, src_ptr) \
    asm volatile("cp.async.cg.shared.global [%0], [%1], 16;" \
        :: "r"(dst_u32), "l"(src_ptr))
#define CP_ASYNC_COMMIT() asm volatile("cp.async.commit_group;" ::: "memory")
#define CP_ASYNC_WAIT(N)  asm volatile("cp.async.wait_group %0;" :: "n"(N) : "memory")

// ============================================================================
// Fused elementwise fp32 -> fp16 over x, w_qkv, w_o (one launch)
// ============================================================================
#define N4_X  (MSEQ * Hv / 4)     // 1048576
#define N4_WQ (H3 * Hv / 4)       // 786432
#define N4_WO (Hv * Hv / 4)       // 262144
#define N4_ALL (N4_X + N4_WQ + N4_WO)

__global__ __launch_bounds__(256)
void cvt_all_kernel(const float* __restrict__ x, const float* __restrict__ wq,
                    const float* __restrict__ wo,
                    __half* __restrict__ dx, __half* __restrict__ dwq,
                    __half* __restrict__ dwo)
{
    int i = blockIdx.x * blockDim.x + threadIdx.x;
    if (i >= N4_ALL) return;
    const float* src;
    __half* dst;
    int j;
    if (i < N4_X)             { src = x;  dst = dx;  j = i; }
    else if (i < N4_X + N4_WQ){ src = wq; dst = dwq; j = i - N4_X; }
    else                      { src = wo; dst = dwo; j = i - N4_X - N4_WQ; }
    float4 v = ((const float4*)src)[j];
    uint2 o;
    o.x = pack_h2(v.x, v.y);
    o.y = pack_h2(v.z, v.w);
    ((uint2*)dst)[j] = o;
}

// ============================================================================
// fp16 GEMM (NT): C[m,n] = sum_k A[m,k]*W[n,k] + bias[n]
// CTA 128x128, KC=64, 3-stage cp.async pipeline (one sync/iter), 2 CTAs/SM.
// ============================================================================
#define SRB   144                // smem row stride bytes (64 fp16 + 16B pad)
#define MATB  (128 * SRB)        // one 128x64 fp16 matrix: 18432 B
#define STGB  (2 * MATB)         // A, W: 36864 B per stage
#define GSM_TOTAL (3 * STGB)     // 3 stages: 110592 B

template<int OUT_HALF>
__global__ __launch_bounds__(256, 2)
void gemm_f16(const __half* __restrict__ A, const __half* __restrict__ W,
              const float* __restrict__ bias, float* __restrict__ C,
              __half* __restrict__ Ch, int M, int N, int K)
{
    extern __shared__ char smem[];
    const uint32_t smb = smem_to_u32(smem);
    const int tid = threadIdx.x;
    const int lid = tid & 31;
    const int wid = tid >> 5;
    const int wm  = wid & 3;
    const int wn  = wid >> 2;
    const int m0  = blockIdx.y * 128;
    const int n0  = blockIdx.x * 128;

    const uint32_t aoff = (uint32_t)((wm * 32 + (lid & 7) + ((lid >> 3) & 1) * 8) * SRB
                                     + (lid >> 4) * 16);
    const uint32_t boff = (uint32_t)((wn * 64 + (lid & 7) + (lid >> 4) * 8) * SRB
                                     + ((lid >> 3) & 1) * 16);

    float acc[2][8][4];
#pragma unroll
    for (int i = 0; i < 2; i++)
#pragma unroll
        for (int j = 0; j < 8; j++)
#pragma unroll
            for (int e = 0; e < 4; e++) acc[i][j][e] = 0.f;

    auto LOAD = [&](int buf, int chunk) {
        const uint32_t base = smb + buf * STGB;
        const int k0 = chunk * 64;
#pragma unroll
        for (int i = 0; i < 8; i++) {
            int idx = tid + i * 256;
            int mat = idx >> 10;
            int rem = idx & 1023;
            int r = rem >> 3;
            int c = rem & 7;
            const __half* src = mat
                ? W + (size_t)(n0 + r) * K + k0 + c * 8
                : A + (size_t)(m0 + r) * K + k0 + c * 8;
            CP_ASYNC16(base + (uint32_t)(mat * MATB + r * SRB + c * 16), src);
        }
        CP_ASYNC_COMMIT();
    };

    auto MMA = [&](int buf) {
        const uint32_t base = smb + buf * STGB;
#pragma unroll
        for (int kt = 0; kt < 4; kt++) {
            uint32_t a0[4], a1[4];
            ldsm_x4(base + aoff + kt * 32, a0);
            ldsm_x4(base + aoff + 16 * SRB + kt * 32, a1);
#pragma unroll
            for (int gn = 0; gn < 4; gn++) {
                uint32_t bb[4];
                ldsm_x4(base + MATB + boff + gn * (16 * SRB) + kt * 32, bb);
                mma_f16(acc[0][2 * gn],     a0, bb[0], bb[1]);
                mma_f16(acc[0][2 * gn + 1], a0, bb[2], bb[3]);
                mma_f16(acc[1][2 * gn],     a1, bb[0], bb[1]);
                mma_f16(acc[1][2 * gn + 1], a1, bb[2], bb[3]);
            }
        }
    };

    const int NCHUNK = K / 64;
    LOAD(0, 0);
    LOAD(1, 1);

    for (int i = 0; i < NCHUNK; i++) {
        if (i + 1 < NCHUNK) { CP_ASYNC_WAIT(1); } else { CP_ASYNC_WAIT(0); }
        __syncthreads();
        if (i + 2 < NCHUNK) LOAD((i + 2) % 3, i + 2);
        MMA(i % 3);
    }

    // ---- Epilogue ----
#pragma unroll
    for (int mt = 0; mt < 2; mt++) {
        const int row = m0 + wm * 32 + mt * 16 + (lid >> 2);
#pragma unroll
        for (int nt = 0; nt < 8; nt++) {
            const int col = n0 + wn * 64 + nt * 8 + (lid & 3) * 2;
            const float b0 = bias[col], b1 = bias[col + 1];
            float v00 = acc[mt][nt][0] + b0, v01 = acc[mt][nt][1] + b1;
            float v10 = acc[mt][nt][2] + b0, v11 = acc[mt][nt][3] + b1;
            if (OUT_HALF) {
                *(uint32_t*)(Ch + (size_t)row * N + col)       = pack_h2(v00, v01);
                *(uint32_t*)(Ch + (size_t)(row + 8) * N + col) = pack_h2(v10, v11);
            } else {
                *(float2*)(C + (size_t)row * N + col)       = make_float2(v00, v01);
                *(float2*)(C + (size_t)(row + 8) * N + col) = make_float2(v10, v11);
            }
        }
    }
}

// ============================================================================
// fp16 tensor-core flash attention.
// CTA: 128 q-rows x one (b,h). 8 warps x 16 q-rows. K-tile = 64 keys.
// Triple-buffered K/V via cp.async -> ONE __syncthreads per tile.
// SMEM 80KB -> 2 CTAs/SM.
// ============================================================================
#define SRA   144                 // fp16 tile row stride bytes
#define QTB   (128 * SRA)         // 18432
#define KVTB  (64 * SRA)          // 9216
#define AS_Q  0
#define AS_KV QTB                          // 3 buf x (K,V): 6 x 9216 = 55296
#define AS_MS (AS_KV + 3 * 2 * KVTB)       // 73728
#define ATT_SMEM (AS_MS + Sv * 4)          // +8192 = 81920

__global__ __launch_bounds__(256, 2)
void attn_mma(const __half* __restrict__ qkv, const float* __restrict__ mask,
              __half* __restrict__ av)
{
    extern __shared__ char smem[];
    const uint32_t smb = smem_to_u32(smem);
    const int tid = threadIdx.x;
    const int lid = tid & 31;
    const int wq  = tid >> 5;
    const int q0  = blockIdx.x * 128;
    const int h   = blockIdx.y;
    const int b   = blockIdx.z;
    const size_t rowbase = (size_t)b * Sv;
    const int hd0 = h * HDv;

    // KV tile loader into buffer buf (one commit group)
    auto LOADKV = [&](int buf, int tile) {
        const int kb = tile * 64;
        const uint32_t kvb = smb + AS_KV + buf * (2 * KVTB);
#pragma unroll
        for (int i = 0; i < 4; i++) {
            int idx = tid + i * 256;
            int mat = idx >> 9;                  // 0:K 1:V
            int rem = idx & 511;
            int r = rem >> 3, c = rem & 7;
            int off = mat ? 2 * Hv : Hv;
            CP_ASYNC16(kvb + mat * KVTB + r * SRA + c * 16,
                       qkv + (rowbase + kb + r) * H3 + off + hd0 + c * 8);
        }
        CP_ASYNC_COMMIT();
    };

    // ---- group 0: mask + Q + KV tile 0; group 1: KV tile 1 ----
#pragma unroll
    for (int i = 0; i < 2; i++) {
        int idx = tid + i * 256;
        CP_ASYNC16(smb + AS_MS + idx * 16, mask + idx * 4);
    }
#pragma unroll
    for (int i = 0; i < 4; i++) {
        int idx = tid + i * 256;
        int r = idx >> 3, c = idx & 7;
        CP_ASYNC16(smb + AS_Q + r * SRA + c * 16,
                   qkv + (rowbase + q0 + r) * H3 + hd0 + c * 8);
    }
    {
        const int kb = 0;
        const uint32_t kvb = smb + AS_KV;
#pragma unroll
        for (int i = 0; i < 4; i++) {
            int idx = tid + i * 256;
            int mat = idx >> 9;
            int rem = idx & 511;
            int r = rem >> 3, c = rem & 7;
            int off = mat ? 2 * Hv : Hv;
            CP_ASYNC16(kvb + mat * KVTB + r * SRA + c * 16,
                       qkv + (rowbase + kb + r) * H3 + off + hd0 + c * 8);
        }
        CP_ASYNC_COMMIT();
    }
    LOADKV(1, 1);

    const uint32_t aoffQ = (uint32_t)((wq * 16 + (lid & 7) + ((lid >> 3) & 1) * 8) * SRA
                                      + (lid >> 4) * 16);
    const uint32_t boffK = (uint32_t)(((lid & 7) + (lid >> 4) * 8) * SRA
                                      + ((lid >> 3) & 1) * 16);
    const uint32_t voffV = (uint32_t)(((lid & 7) + ((lid >> 3) & 1) * 8) * SRA
                                      + (lid >> 4) * 16);

    float o[8][4];
#pragma unroll
    for (int j = 0; j < 8; j++)
#pragma unroll
        for (int e = 0; e < 4; e++) o[j][e] = 0.f;
    float m0 = -INFINITY, m1 = -INFINITY, l0 = 0.f, l1 = 0.f;

    const int NT = Sv / 64;
    for (int t = 0; t < NT; t++) {
        if (t + 1 < NT) { CP_ASYNC_WAIT(1); } else { CP_ASYNC_WAIT(0); }
        __syncthreads();
        if (t + 2 < NT) LOADKV((t + 2) % 3, t + 2);

        const uint32_t kvb = smb + AS_KV + (t % 3) * (2 * KVTB);
        const uint32_t KB = kvb, VB = kvb + KVTB;

        // ---- S = Q K^T ----
        float s[8][4];
#pragma unroll
        for (int j = 0; j < 8; j++)
#pragma unroll
            for (int e = 0; e < 4; e++) s[j][e] = 0.f;

#pragma unroll
        for (int kt = 0; kt < 4; kt++) {
            uint32_t aQ[4];
            ldsm_x4(smb + AS_Q + aoffQ + kt * 32, aQ);
#pragma unroll
            for (int gn = 0; gn < 4; gn++) {
                uint32_t bb[4];
                ldsm_x4(KB + boffK + gn * (16 * SRA) + kt * 32, bb);
                mma_f16(s[2 * gn],     aQ, bb[0], bb[1]);
                mma_f16(s[2 * gn + 1], aQ, bb[2], bb[3]);
            }
        }

        // ---- online softmax ----
        const uint32_t msb = smb + AS_MS + (uint32_t)((t * 64 + 2 * (lid & 3)) * 4);
        float tm0 = -INFINITY, tm1 = -INFINITY;
#pragma unroll
        for (int j = 0; j < 8; j++) {
            float mkx, mky;
            asm("ld.shared.v2.f32 {%0,%1}, [%2];" : "=f"(mkx), "=f"(mky) : "r"(msb + j * 32));
            s[j][0] = (s[j][0] + mkx) * 0.125f;
            s[j][1] = (s[j][1] + mky) * 0.125f;
            s[j][2] = (s[j][2] + mkx) * 0.125f;
            s[j][3] = (s[j][3] + mky) * 0.125f;
            tm0 = fmaxf(tm0, fmaxf(s[j][0], s[j][1]));
            tm1 = fmaxf(tm1, fmaxf(s[j][2], s[j][3]));
        }
        tm0 = fmaxf(tm0, __shfl_xor_sync(0xffffffffu, tm0, 1));
        tm0 = fmaxf(tm0, __shfl_xor_sync(0xffffffffu, tm0, 2));
        tm1 = fmaxf(tm1, __shfl_xor_sync(0xffffffffu, tm1, 1));
        tm1 = fmaxf(tm1, __shfl_xor_sync(0xffffffffu, tm1, 2));

        const float mn0 = fmaxf(m0, tm0), mn1 = fmaxf(m1, tm1);
        const float al0 = __expf(m0 - mn0), al1 = __expf(m1 - mn1);
        m0 = mn0; m1 = mn1;

        float rs0 = 0.f, rs1 = 0.f;
#pragma unroll
        for (int j = 0; j < 8; j++) {
            s[j][0] = __expf(s[j][0] - mn0);
            s[j][1] = __expf(s[j][1] - mn0);
            s[j][2] = __expf(s[j][2] - mn1);
            s[j][3] = __expf(s[j][3] - mn1);
            rs0 += s[j][0] + s[j][1];
            rs1 += s[j][2] + s[j][3];
        }
        rs0 += __shfl_xor_sync(0xffffffffu, rs0, 1);
        rs0 += __shfl_xor_sync(0xffffffffu, rs0, 2);
        rs1 += __shfl_xor_sync(0xffffffffu, rs1, 1);
        rs1 += __shfl_xor_sync(0xffffffffu, rs1, 2);
        l0 = l0 * al0 + rs0;
        l1 = l1 * al1 + rs1;

#pragma unroll
        for (int j = 0; j < 8; j++) {
            o[j][0] *= al0; o[j][1] *= al0;
            o[j][2] *= al1; o[j][3] *= al1;
        }

        // ---- O += P V ----
#pragma unroll
        for (int kt = 0; kt < 4; kt++) {
            uint32_t ap[4];
            ap[0] = pack_h2(s[2 * kt][0],     s[2 * kt][1]);
            ap[1] = pack_h2(s[2 * kt][2],     s[2 * kt][3]);
            ap[2] = pack_h2(s[2 * kt + 1][0], s[2 * kt + 1][1]);
            ap[3] = pack_h2(s[2 * kt + 1][2], s[2 * kt + 1][3]);
#pragma unroll
            for (int jp = 0; jp < 4; jp++) {
                uint32_t bb[4];
                ldsm_x4_t(VB + voffV + kt * (16 * SRA) + jp * 32, bb);
                mma_f16(o[2 * jp],     ap, bb[0], bb[1]);
                mma_f16(o[2 * jp + 1], ap, bb[2], bb[3]);
            }
        }
    }

    // ---- Epilogue: normalize, store fp16 av ----
    const float inv0 = 1.f / l0, inv1 = 1.f / l1;
    const int rg = q0 + wq * 16 + (lid >> 2);
    const size_t obase = (rowbase + rg) * Hv + hd0 + 2 * (lid & 3);
#pragma unroll
    for (int j = 0; j < 8; j++) {
        *(uint32_t*)(av + obase + j * 8)          = pack_h2(o[j][0] * inv0, o[j][1] * inv0);
        *(uint32_t*)(av + obase + 8 * Hv + j * 8) = pack_h2(o[j][2] * inv1, o[j][3] * inv1);
    }
}

// ============================================================================
// Launch
// ============================================================================
extern "C" void kernel_launch(void* const* d_in, const int* in_sizes, int n_in,
                              void* d_out, int out_size)
{
    const float* x     = (const float*)d_in[0];
    const float* mask  = (const float*)d_in[1];
    const float* w_qkv = (const float*)d_in[2];
    const float* b_qkv = (const float*)d_in[3];
    const float* w_o   = (const float*)d_in[4];
    const float* b_o   = (const float*)d_in[5];
    float* out = (float*)d_out;

    __half *p_x, *p_wq, *p_wo, *p_qkv, *p_av;
    cudaGetSymbolAddress((void**)&p_x, g_x);
    cudaGetSymbolAddress((void**)&p_wq, g_wq);
    cudaGetSymbolAddress((void**)&p_wo, g_wo);
    cudaGetSymbolAddress((void**)&p_qkv, g_qkv);
    cudaGetSymbolAddress((void**)&p_av, g_av);

    cudaFuncSetAttribute(gemm_f16<1>,
                         cudaFuncAttributeMaxDynamicSharedMemorySize, GSM_TOTAL);
    cudaFuncSetAttribute(gemm_f16<0>,
                         cudaFuncAttributeMaxDynamicSharedMemorySize, GSM_TOTAL);
    cudaFuncSetAttribute(attn_mma,
                         cudaFuncAttributeMaxDynamicSharedMemorySize, ATT_SMEM);

    // 0) Convert all fp32 inputs to fp16 (one launch)
    cvt_all_kernel<<<(N4_ALL + 255) / 256, 256>>>(x, w_qkv, w_o, p_x, p_wq, p_wo);

    // 1) QKV projection -> fp16 qkv
    dim3 g1(H3 / 128, MSEQ / 128);
    gemm_f16<1><<<g1, 256, GSM_TOTAL>>>(p_x, p_wq, b_qkv, nullptr, p_qkv,
                                        MSEQ, H3, Hv);

    // 2) fp16 flash attention -> fp16 av
    attn_mma<<<dim3(Sv / 128, NHv, Bv), 256, ATT_SMEM>>>(p_qkv, mask, p_av);

    // 3) Output projection -> fp32 out
    dim3 g2(Hv / 128, MSEQ / 128);
    gemm_f16<0><<<g2, 256, GSM_TOTAL>>>(p_av, p_wo, b_o, out, nullptr,
                                        MSEQ, Hv, Hv);
}

// round 9
// speedup vs baseline: 6.7826x; 1.0236x over previous
#include <cuda_runtime.h>
#include <cuda_fp16.h>
#include <math.h>
#include <stdint.h>

// Problem constants
#define Bv   2
#define Sv   2048
#define Hv   1024
#define NHv  16
#define HDv  64
#define H3   (3 * Hv)
#define MSEQ (Bv * Sv)          // 4096 rows

// softmax scale folded into Q and mask: (1/8) * log2(e)
#define QSCALE 0.18033688011112042f

// Scratch (device globals: allocation-guard safe)
__device__ __half g_x [(size_t)MSEQ * Hv];
__device__ __half g_wq[(size_t)H3 * Hv];
__device__ __half g_wo[(size_t)Hv * Hv];
__device__ __half g_qkv[(size_t)MSEQ * H3];
__device__ __half g_av[(size_t)MSEQ * Hv];
__device__ float  g_mask[Sv];            // mask * QSCALE

// ============================================================================
// Helpers
// ============================================================================
__device__ __forceinline__ uint32_t smem_to_u32(const void* smem_ptr) {
    uint32_t addr;
    asm("{ .reg .u64 tmp; cvta.to.shared.u64 tmp, %1; cvt.u32.u64 %0, tmp; }"
        : "=r"(addr) : "l"(smem_ptr));
    return addr;
}

__device__ __forceinline__ void ldsm_x4(uint32_t addr, uint32_t r[4]) {
    asm volatile("ldmatrix.sync.aligned.m8n8.x4.shared.b16 {%0,%1,%2,%3}, [%4];"
        : "=r"(r[0]), "=r"(r[1]), "=r"(r[2]), "=r"(r[3]) : "r"(addr));
}

__device__ __forceinline__ void ldsm_x4_t(uint32_t addr, uint32_t r[4]) {
    asm volatile("ldmatrix.sync.aligned.m8n8.x4.trans.shared.b16 {%0,%1,%2,%3}, [%4];"
        : "=r"(r[0]), "=r"(r[1]), "=r"(r[2]), "=r"(r[3]) : "r"(addr));
}

__device__ __forceinline__ void mma_f16(float d[4], const uint32_t a[4],
                                        uint32_t b0, uint32_t b1) {
    asm volatile(
        "mma.sync.aligned.m16n8k16.row.col.f32.f16.f16.f32 "
        "{%0,%1,%2,%3}, {%4,%5,%6,%7}, {%8,%9}, {%0,%1,%2,%3};"
        : "+f"(d[0]), "+f"(d[1]), "+f"(d[2]), "+f"(d[3])
        : "r"(a[0]), "r"(a[1]), "r"(a[2]), "r"(a[3]), "r"(b0), "r"(b1));
}

__device__ __forceinline__ uint32_t pack_h2(float x, float y) {
    __half2 h = __float22half2_rn(make_float2(x, y));
    return *(uint32_t*)&h;
}

#define CP_ASYNC16(dst_u32, src_ptr) \
    asm volatile("cp.async.cg.shared.global [%0], [%1], 16;" \
        :: "r"(dst_u32), "l"(src_ptr))
#define CP_ASYNC_COMMIT() asm volatile("cp.async.commit_group;" ::: "memory")
#define CP_ASYNC_WAIT(N)  asm volatile("cp.async.wait_group %0;" :: "n"(N) : "memory")

// ============================================================================
// Fused elementwise: fp32->fp16 for x, w_qkv, w_o; mask -> mask*QSCALE (fp32)
// ============================================================================
#define N4_X   (MSEQ * Hv / 4)
#define N4_WQ  (H3 * Hv / 4)
#define N4_WO  (Hv * Hv / 4)
#define N4_MS  (Sv / 4)
#define N4_ALL (N4_X + N4_WQ + N4_WO + N4_MS)

__global__ __launch_bounds__(256)
void cvt_all_kernel(const float* __restrict__ x, const float* __restrict__ wq,
                    const float* __restrict__ wo, const float* __restrict__ mask,
                    __half* __restrict__ dx, __half* __restrict__ dwq,
                    __half* __restrict__ dwo, float* __restrict__ dmask)
{
    int i = blockIdx.x * blockDim.x + threadIdx.x;
    if (i >= N4_ALL) return;
    if (i >= N4_X + N4_WQ + N4_WO) {
        int j = i - (N4_X + N4_WQ + N4_WO);
        float4 v = ((const float4*)mask)[j];
        v.x *= QSCALE; v.y *= QSCALE; v.z *= QSCALE; v.w *= QSCALE;
        ((float4*)dmask)[j] = v;
        return;
    }
    const float* src;
    __half* dst;
    int j;
    if (i < N4_X)              { src = x;  dst = dx;  j = i; }
    else if (i < N4_X + N4_WQ) { src = wq; dst = dwq; j = i - N4_X; }
    else                       { src = wo; dst = dwo; j = i - N4_X - N4_WQ; }
    float4 v = ((const float4*)src)[j];
    uint2 o;
    o.x = pack_h2(v.x, v.y);
    o.y = pack_h2(v.z, v.w);
    ((uint2*)dst)[j] = o;
}

// ============================================================================
// fp16 GEMM (NT): C[m,n] = sum_k A[m,k]*W[n,k] + bias[n]
// CTA 128x128, KC=64, 3-stage cp.async pipeline, 2 CTAs/SM.
// OUT_HALF=1 (qkv): Q columns (col < Hv) scaled by QSCALE after bias.
// ============================================================================
#define SRB   144
#define MATB  (128 * SRB)
#define STGB  (2 * MATB)
#define GSM_TOTAL (3 * STGB)     // 110592 B

template<int OUT_HALF>
__global__ __launch_bounds__(256, 2)
void gemm_f16(const __half* __restrict__ A, const __half* __restrict__ W,
              const float* __restrict__ bias, float* __restrict__ C,
              __half* __restrict__ Ch, int M, int N, int K)
{
    extern __shared__ char smem[];
    const uint32_t smb = smem_to_u32(smem);
    const int tid = threadIdx.x;
    const int lid = tid & 31;
    const int wid = tid >> 5;
    const int wm  = wid & 3;
    const int wn  = wid >> 2;
    const int m0  = blockIdx.y * 128;
    const int n0  = blockIdx.x * 128;

    const uint32_t aoff = (uint32_t)((wm * 32 + (lid & 7) + ((lid >> 3) & 1) * 8) * SRB
                                     + (lid >> 4) * 16);
    const uint32_t boff = (uint32_t)((wn * 64 + (lid & 7) + (lid >> 4) * 8) * SRB
                                     + ((lid >> 3) & 1) * 16);

    float acc[2][8][4];
#pragma unroll
    for (int i = 0; i < 2; i++)
#pragma unroll
        for (int j = 0; j < 8; j++)
#pragma unroll
            for (int e = 0; e < 4; e++) acc[i][j][e] = 0.f;

    auto LOAD = [&](int buf, int chunk) {
        const uint32_t base = smb + buf * STGB;
        const int k0 = chunk * 64;
#pragma unroll
        for (int i = 0; i < 8; i++) {
            int idx = tid + i * 256;
            int mat = idx >> 10;
            int rem = idx & 1023;
            int r = rem >> 3;
            int c = rem & 7;
            const __half* src = mat
                ? W + (size_t)(n0 + r) * K + k0 + c * 8
                : A + (size_t)(m0 + r) * K + k0 + c * 8;
            CP_ASYNC16(base + (uint32_t)(mat * MATB + r * SRB + c * 16), src);
        }
        CP_ASYNC_COMMIT();
    };

    auto MMA = [&](int buf) {
        const uint32_t base = smb + buf * STGB;
#pragma unroll
        for (int kt = 0; kt < 4; kt++) {
            uint32_t a0[4], a1[4];
            ldsm_x4(base + aoff + kt * 32, a0);
            ldsm_x4(base + aoff + 16 * SRB + kt * 32, a1);
#pragma unroll
            for (int gn = 0; gn < 4; gn++) {
                uint32_t bb[4];
                ldsm_x4(base + MATB + boff + gn * (16 * SRB) + kt * 32, bb);
                mma_f16(acc[0][2 * gn],     a0, bb[0], bb[1]);
                mma_f16(acc[0][2 * gn + 1], a0, bb[2], bb[3]);
                mma_f16(acc[1][2 * gn],     a1, bb[0], bb[1]);
                mma_f16(acc[1][2 * gn + 1], a1, bb[2], bb[3]);
            }
        }
    };

    const int NCHUNK = K / 64;
    LOAD(0, 0);
    LOAD(1, 1);

    for (int i = 0; i < NCHUNK; i++) {
        if (i + 1 < NCHUNK) { CP_ASYNC_WAIT(1); } else { CP_ASYNC_WAIT(0); }
        __syncthreads();
        if (i + 2 < NCHUNK) LOAD((i + 2) % 3, i + 2);
        MMA(i % 3);
    }

    // ---- Epilogue ----
#pragma unroll
    for (int mt = 0; mt < 2; mt++) {
        const int row = m0 + wm * 32 + mt * 16 + (lid >> 2);
#pragma unroll
        for (int nt = 0; nt < 8; nt++) {
            const int col = n0 + wn * 64 + nt * 8 + (lid & 3) * 2;
            const float b0 = bias[col], b1 = bias[col + 1];
            float v00 = acc[mt][nt][0] + b0, v01 = acc[mt][nt][1] + b1;
            float v10 = acc[mt][nt][2] + b0, v11 = acc[mt][nt][3] + b1;
            if (OUT_HALF) {
                // Q columns carry the softmax scale (exact through the matmul)
                const float sc = (col < Hv) ? QSCALE : 1.0f;
                v00 *= sc; v01 *= sc; v10 *= sc; v11 *= sc;
                *(uint32_t*)(Ch + (size_t)row * N + col)       = pack_h2(v00, v01);
                *(uint32_t*)(Ch + (size_t)(row + 8) * N + col) = pack_h2(v10, v11);
            } else {
                *(float2*)(C + (size_t)row * N + col)       = make_float2(v00, v01);
                *(float2*)(C + (size_t)(row + 8) * N + col) = make_float2(v10, v11);
            }
        }
    }
}

// ============================================================================
// fp16 tensor-core flash attention; scores arrive in log2-domain.
// Triple-buffered K/V, one sync per tile, 2 CTAs/SM.
// ============================================================================
#define SRA   144
#define QTB   (128 * SRA)
#define KVTB  (64 * SRA)
#define AS_Q  0
#define AS_KV QTB
#define AS_MS (AS_KV + 3 * 2 * KVTB)
#define ATT_SMEM (AS_MS + Sv * 4)          // 81920

__global__ __launch_bounds__(256, 2)
void attn_mma(const __half* __restrict__ qkv, const float* __restrict__ masks,
              __half* __restrict__ av)
{
    extern __shared__ char smem[];
    const uint32_t smb = smem_to_u32(smem);
    const int tid = threadIdx.x;
    const int lid = tid & 31;
    const int wq  = tid >> 5;
    const int q0  = blockIdx.x * 128;
    const int h   = blockIdx.y;
    const int b   = blockIdx.z;
    const size_t rowbase = (size_t)b * Sv;
    const int hd0 = h * HDv;

    auto LOADKV = [&](int buf, int tile) {
        const int kb = tile * 64;
        const uint32_t kvb = smb + AS_KV + buf * (2 * KVTB);
#pragma unroll
        for (int i = 0; i < 4; i++) {
            int idx = tid + i * 256;
            int mat = idx >> 9;
            int rem = idx & 511;
            int r = rem >> 3, c = rem & 7;
            int off = mat ? 2 * Hv : Hv;
            CP_ASYNC16(kvb + mat * KVTB + r * SRA + c * 16,
                       qkv + (rowbase + kb + r) * H3 + off + hd0 + c * 8);
        }
        CP_ASYNC_COMMIT();
    };

    // group 0: mask + Q + KV tile 0; group 1: KV tile 1
#pragma unroll
    for (int i = 0; i < 2; i++) {
        int idx = tid + i * 256;
        CP_ASYNC16(smb + AS_MS + idx * 16, masks + idx * 4);
    }
#pragma unroll
    for (int i = 0; i < 4; i++) {
        int idx = tid + i * 256;
        int r = idx >> 3, c = idx & 7;
        CP_ASYNC16(smb + AS_Q + r * SRA + c * 16,
                   qkv + (rowbase + q0 + r) * H3 + hd0 + c * 8);
    }
    {
        const uint32_t kvb = smb + AS_KV;
#pragma unroll
        for (int i = 0; i < 4; i++) {
            int idx = tid + i * 256;
            int mat = idx >> 9;
            int rem = idx & 511;
            int r = rem >> 3, c = rem & 7;
            int off = mat ? 2 * Hv : Hv;
            CP_ASYNC16(kvb + mat * KVTB + r * SRA + c * 16,
                       qkv + (rowbase + r) * H3 + off + hd0 + c * 8);
        }
        CP_ASYNC_COMMIT();
    }
    LOADKV(1, 1);

    const uint32_t aoffQ = (uint32_t)((wq * 16 + (lid & 7) + ((lid >> 3) & 1) * 8) * SRA
                                      + (lid >> 4) * 16);
    const uint32_t boffK = (uint32_t)(((lid & 7) + (lid >> 4) * 8) * SRA
                                      + ((lid >> 3) & 1) * 16);
    const uint32_t voffV = (uint32_t)(((lid & 7) + ((lid >> 3) & 1) * 8) * SRA
                                      + (lid >> 4) * 16);

    float o[8][4];
#pragma unroll
    for (int j = 0; j < 8; j++)
#pragma unroll
        for (int e = 0; e < 4; e++) o[j][e] = 0.f;
    float m0 = -INFINITY, m1 = -INFINITY, l0 = 0.f, l1 = 0.f;

    const int NT = Sv / 64;
    for (int t = 0; t < NT; t++) {
        if (t + 1 < NT) { CP_ASYNC_WAIT(1); } else { CP_ASYNC_WAIT(0); }
        __syncthreads();
        if (t + 2 < NT) LOADKV((t + 2) % 3, t + 2);

        const uint32_t kvb = smb + AS_KV + (t % 3) * (2 * KVTB);
        const uint32_t KB = kvb, VB = kvb + KVTB;

        // ---- S = Q K^T (already log2-scaled via Q) ----
        float s[8][4];
#pragma unroll
        for (int j = 0; j < 8; j++)
#pragma unroll
            for (int e = 0; e < 4; e++) s[j][e] = 0.f;

#pragma unroll
        for (int kt = 0; kt < 4; kt++) {
            uint32_t aQ[4];
            ldsm_x4(smb + AS_Q + aoffQ + kt * 32, aQ);
#pragma unroll
            for (int gn = 0; gn < 4; gn++) {
                uint32_t bb[4];
                ldsm_x4(KB + boffK + gn * (16 * SRA) + kt * 32, bb);
                mma_f16(s[2 * gn],     aQ, bb[0], bb[1]);
                mma_f16(s[2 * gn + 1], aQ, bb[2], bb[3]);
            }
        }

        // ---- online softmax (log2 domain: exp2 only) ----
        const uint32_t msb = smb + AS_MS + (uint32_t)((t * 64 + 2 * (lid & 3)) * 4);
        float tm0 = -INFINITY, tm1 = -INFINITY;
#pragma unroll
        for (int j = 0; j < 8; j++) {
            float mkx, mky;
            asm("ld.shared.v2.f32 {%0,%1}, [%2];" : "=f"(mkx), "=f"(mky) : "r"(msb + j * 32));
            s[j][0] += mkx;
            s[j][1] += mky;
            s[j][2] += mkx;
            s[j][3] += mky;
            tm0 = fmaxf(tm0, fmaxf(s[j][0], s[j][1]));
            tm1 = fmaxf(tm1, fmaxf(s[j][2], s[j][3]));
        }
        tm0 = fmaxf(tm0, __shfl_xor_sync(0xffffffffu, tm0, 1));
        tm0 = fmaxf(tm0, __shfl_xor_sync(0xffffffffu, tm0, 2));
        tm1 = fmaxf(tm1, __shfl_xor_sync(0xffffffffu, tm1, 1));
        tm1 = fmaxf(tm1, __shfl_xor_sync(0xffffffffu, tm1, 2));

        float al0 = 1.f, al1 = 1.f;
        const bool need = (tm0 > m0) || (tm1 > m1);
        if (__any_sync(0xffffffffu, need)) {
            const float mn0 = fmaxf(m0, tm0), mn1 = fmaxf(m1, tm1);
            al0 = exp2f(m0 - mn0);
            al1 = exp2f(m1 - mn1);
            m0 = mn0; m1 = mn1;
#pragma unroll
            for (int j = 0; j < 8; j++) {
                o[j][0] *= al0; o[j][1] *= al0;
                o[j][2] *= al1; o[j][3] *= al1;
            }
        }

        float rs0 = 0.f, rs1 = 0.f;
#pragma unroll
        for (int j = 0; j < 8; j++) {
            s[j][0] = exp2f(s[j][0] - m0);
            s[j][1] = exp2f(s[j][1] - m0);
            s[j][2] = exp2f(s[j][2] - m1);
            s[j][3] = exp2f(s[j][3] - m1);
            rs0 += s[j][0] + s[j][1];
            rs1 += s[j][2] + s[j][3];
        }
        rs0 += __shfl_xor_sync(0xffffffffu, rs0, 1);
        rs0 += __shfl_xor_sync(0xffffffffu, rs0, 2);
        rs1 += __shfl_xor_sync(0xffffffffu, rs1, 1);
        rs1 += __shfl_xor_sync(0xffffffffu, rs1, 2);
        l0 = l0 * al0 + rs0;
        l1 = l1 * al1 + rs1;

        // ---- O += P V ----
#pragma unroll
        for (int kt = 0; kt < 4; kt++) {
            uint32_t ap[4];
            ap[0] = pack_h2(s[2 * kt][0],     s[2 * kt][1]);
            ap[1] = pack_h2(s[2 * kt][2],     s[2 * kt][3]);
            ap[2] = pack_h2(s[2 * kt + 1][0], s[2 * kt + 1][1]);
            ap[3] = pack_h2(s[2 * kt + 1][2], s[2 * kt + 1][3]);
#pragma unroll
            for (int jp = 0; jp < 4; jp++) {
                uint32_t bb[4];
                ldsm_x4_t(VB + voffV + kt * (16 * SRA) + jp * 32, bb);
                mma_f16(o[2 * jp],     ap, bb[0], bb[1]);
                mma_f16(o[2 * jp + 1], ap, bb[2], bb[3]);
            }
        }
    }

    // ---- Epilogue ----
    const float inv0 = 1.f / l0, inv1 = 1.f / l1;
    const int rg = q0 + wq * 16 + (lid >> 2);
    const size_t obase = (rowbase + rg) * Hv + hd0 + 2 * (lid & 3);
#pragma unroll
    for (int j = 0; j < 8; j++) {
        *(uint32_t*)(av + obase + j * 8)          = pack_h2(o[j][0] * inv0, o[j][1] * inv0);
        *(uint32_t*)(av + obase + 8 * Hv + j * 8) = pack_h2(o[j][2] * inv1, o[j][3] * inv1);
    }
}

// ============================================================================
// Launch
// ============================================================================
extern "C" void kernel_launch(void* const* d_in, const int* in_sizes, int n_in,
                              void* d_out, int out_size)
{
    const float* x     = (const float*)d_in[0];
    const float* mask  = (const float*)d_in[1];
    const float* w_qkv = (const float*)d_in[2];
    const float* b_qkv = (const float*)d_in[3];
    const float* w_o   = (const float*)d_in[4];
    const float* b_o   = (const float*)d_in[5];
    float* out = (float*)d_out;

    __half *p_x, *p_wq, *p_wo, *p_qkv, *p_av;
    float* p_mask;
    cudaGetSymbolAddress((void**)&p_x, g_x);
    cudaGetSymbolAddress((void**)&p_wq, g_wq);
    cudaGetSymbolAddress((void**)&p_wo, g_wo);
    cudaGetSymbolAddress((void**)&p_qkv, g_qkv);
    cudaGetSymbolAddress((void**)&p_av, g_av);
    cudaGetSymbolAddress((void**)&p_mask, g_mask);

    cudaFuncSetAttribute(gemm_f16<1>,
                         cudaFuncAttributeMaxDynamicSharedMemorySize, GSM_TOTAL);
    cudaFuncSetAttribute(gemm_f16<0>,
                         cudaFuncAttributeMaxDynamicSharedMemorySize, GSM_TOTAL);
    cudaFuncSetAttribute(attn_mma,
                         cudaFuncAttributeMaxDynamicSharedMemorySize, ATT_SMEM);

    // 0) Convert inputs (one launch): x/wq/wo -> fp16, mask -> mask*QSCALE
    cvt_all_kernel<<<(N4_ALL + 255) / 256, 256>>>(x, w_qkv, w_o, mask,
                                                  p_x, p_wq, p_wo, p_mask);

    // 1) QKV projection -> fp16 qkv (Q pre-scaled by QSCALE)
    dim3 g1(H3 / 128, MSEQ / 128);
    gemm_f16<1><<<g1, 256, GSM_TOTAL>>>(p_x, p_wq, b_qkv, nullptr, p_qkv,
                                        MSEQ, H3, Hv);

    // 2) fp16 flash attention -> fp16 av
    attn_mma<<<dim3(Sv / 128, NHv, Bv), 256, ATT_SMEM>>>(p_qkv, p_mask, p_av);

    // 3) Output projection -> fp32 out
    dim3 g2(Hv / 128, MSEQ / 128);
    gemm_f16<0><<<g2, 256, GSM_TOTAL>>>(p_av, p_wo, b_o, out, nullptr,
                                        MSEQ, Hv, Hv);
}